// round 14
// baseline (speedup 1.0000x reference)
#include <cuda_runtime.h>
#include <cuda_fp16.h>
#include <cstdint>

#define B_  4
#define T_  2048
#define C_  1024
#define NH_ 16
#define D_  64
#define M_  (B_*T_)
#define NX  (M_*C_)
#define NW  (C_*C_)

// ---- GEMM smem (halves, pitch 40): 3 tiles/stage (Ah, Wh, Wl), 3 stages ----
#define PH     40
#define TILEB  10240u
#define STAGEB 30720u
#define GSMEM  92160

// ---- Attention smem: Q(h,l) 128x64 + 2 stages x (Kh,Kl,Vh,Vl) 64x64 ----
#define PQ 72
#define KVTILE 9216u               // 64*PQ*2
#define STAGEA 36864u              // 4 KV tiles
#define QH_OFF 0u
#define QL_OFF 18432u
#define ST_OFF 36864u
#define ATT_SMEM 110592

extern __shared__ char dyn_smem[];

// Scratch (static device globals — no allocation at runtime)
__device__ __half g_qh[M_*C_],  g_ql[M_*C_];
__device__ __half g_ah[M_*C_];                  // attention out (hi only)
__device__ __half g_xh[M_*C_];                  // x hi
__device__ __half g_xch[M_*C_];                 // compacted x hi
__device__ __half g_wqh[C_*C_], g_wql[C_*C_];
__device__ __half g_wkh[C_*C_], g_wkl[C_*C_];
__device__ __half g_wvh[C_*C_], g_wvl[C_*C_];
__device__ __half g_wph[C_*C_], g_wpl[C_*C_];
// mask compaction
__device__ int    g_cnt[B_*T_];
__device__ int    g_pos[B_*T_];
// compacted K/V (written directly by K/V GEMM epilogue)
__device__ __half g_kch[M_*C_], g_kcl[M_*C_];
__device__ __half g_vch[M_*C_], g_vcl[M_*C_];

// ---------------------------------------------------------------------------
// helpers
// ---------------------------------------------------------------------------
__device__ __forceinline__ uint32_t smem_to_u32(const void* p) {
    uint32_t a;
    asm("{ .reg .u64 t; cvta.to.shared.u64 t, %1; cvt.u32.u64 %0, t; }"
        : "=r"(a) : "l"(p));
    return a;
}

__device__ __forceinline__ void cp_async16(uint32_t s, const void* g) {
    asm volatile("cp.async.cg.shared.global [%0], [%1], 16;" :: "r"(s), "l"(g));
}
#define CP_COMMIT() asm volatile("cp.async.commit_group;" ::: "memory")

__device__ __forceinline__ void ldmx4(uint32_t& r0, uint32_t& r1,
                                      uint32_t& r2, uint32_t& r3, uint32_t a) {
    asm volatile("ldmatrix.sync.aligned.m8n8.x4.shared.b16 {%0,%1,%2,%3}, [%4];"
                 : "=r"(r0), "=r"(r1), "=r"(r2), "=r"(r3) : "r"(a));
}
__device__ __forceinline__ void ldmx4t(uint32_t& r0, uint32_t& r1,
                                       uint32_t& r2, uint32_t& r3, uint32_t a) {
    asm volatile("ldmatrix.sync.aligned.m8n8.x4.trans.shared.b16 {%0,%1,%2,%3}, [%4];"
                 : "=r"(r0), "=r"(r1), "=r"(r2), "=r"(r3) : "r"(a));
}

__device__ __forceinline__ void mma_f16(float& c0, float& c1, float& c2, float& c3,
                                        uint32_t a0, uint32_t a1, uint32_t a2, uint32_t a3,
                                        uint32_t b0, uint32_t b1) {
    asm volatile(
        "mma.sync.aligned.m16n8k16.row.col.f32.f16.f16.f32 "
        "{%0,%1,%2,%3}, {%4,%5,%6,%7}, {%8,%9}, {%0,%1,%2,%3};\n"
        : "+f"(c0), "+f"(c1), "+f"(c2), "+f"(c3)
        : "r"(a0), "r"(a1), "r"(a2), "r"(a3), "r"(b0), "r"(b1));
}

__device__ __forceinline__ float ex2f(float x) {
    float r;
    asm("ex2.approx.f32 %0, %1;" : "=f"(r) : "f"(x));
    return r;
}

__device__ __forceinline__ uint32_t pack_h2(float x, float y) {
    uint32_t r;
    asm("cvt.rn.f16x2.f32 %0, %1, %2;" : "=r"(r) : "f"(y), "f"(x));
    return r;
}

__device__ __forceinline__ void pack_hl(float x, float y, uint32_t& hh, uint32_t& ll) {
    __half hx = __float2half_rn(x), hy = __float2half_rn(y);
    __half lx = __float2half_rn(x - __half2float(hx));
    __half ly = __float2half_rn(y - __half2float(hy));
    __half2 H = __halves2half2(hx, hy), L = __halves2half2(lx, ly);
    hh = *(uint32_t*)&H; ll = *(uint32_t*)&L;
}

// ---------------------------------------------------------------------------
// fused split prepass: x -> hi only; weights -> (hi, lo)
// ---------------------------------------------------------------------------
__global__ void __launch_bounds__(256) split_all_kernel(
    const float* __restrict__ x,  const float* __restrict__ wq,
    const float* __restrict__ wk, const float* __restrict__ wv,
    const float* __restrict__ wp)
{
    const long long i4 = ((long long)blockIdx.x * 256 + threadIdx.x) * 4;
    if (i4 < (long long)NX) {
        float4 v = *(const float4*)(x + i4);
        *(uint32_t*)(g_xh + i4)     = pack_h2(v.x, v.y);
        *(uint32_t*)(g_xh + i4 + 2) = pack_h2(v.z, v.w);
        return;
    }
    const long long r = i4 - (long long)NX;
    const int wsel = (int)(r >> 20);          // NW == 1<<20
    const long long off = r & (long long)(NW - 1);
    const float* src; __half *dh, *dl;
    switch (wsel) {
        case 0:  src = wq; dh = g_wqh; dl = g_wql; break;
        case 1:  src = wk; dh = g_wkh; dl = g_wkl; break;
        case 2:  src = wv; dh = g_wvh; dl = g_wvl; break;
        default: src = wp; dh = g_wph; dl = g_wpl; break;
    }
    float4 v = *(const float4*)(src + off);
    uint32_t h0, l0, h1, l1;
    pack_hl(v.x, v.y, h0, l0);
    pack_hl(v.z, v.w, h1, l1);
    *(uint32_t*)(dh + off)     = h0;
    *(uint32_t*)(dh + off + 2) = h1;
    *(uint32_t*)(dl + off)     = l0;
    *(uint32_t*)(dl + off + 2) = l1;
}

// ---------------------------------------------------------------------------
// token-mask scan: per batch, inclusive counts + compact position list
// ---------------------------------------------------------------------------
__global__ void __launch_bounds__(256) mask_scan_kernel(const int* __restrict__ tmask)
{
    __shared__ int wsum[8];
    const int b = blockIdx.x;
    const int tid = threadIdx.x;
    const int lane = tid & 31, wid = tid >> 5;
    const int t0 = tid * 8;

    int v[8]; int s = 0;
    #pragma unroll
    for (int i = 0; i < 8; ++i) { v[i] = (tmask[b*T_ + t0 + i] != 0) ? 1 : 0; s += v[i]; }

    int sc = s;
    #pragma unroll
    for (int off = 1; off < 32; off <<= 1) {
        int n = __shfl_up_sync(0xffffffffu, sc, off);
        if (lane >= off) sc += n;
    }
    if (lane == 31) wsum[wid] = sc;
    __syncthreads();
    if (tid == 0) {
        int acc = 0;
        #pragma unroll
        for (int i = 0; i < 8; ++i) { acc += wsum[i]; wsum[i] = acc; }
    }
    __syncthreads();
    const int wbase = (wid > 0) ? wsum[wid - 1] : 0;
    int run = wbase + sc - s;
    #pragma unroll
    for (int i = 0; i < 8; ++i) {
        run += v[i];
        g_cnt[b*T_ + t0 + i] = run;
        if (v[i]) g_pos[b*T_ + run - 1] = t0 + i;
    }
}

// ---------------------------------------------------------------------------
// gather valid x rows (hi) into compacted buffer
// ---------------------------------------------------------------------------
__global__ void __launch_bounds__(128) gather_x_kernel()
{
    const int j = blockIdx.x, b = blockIdx.y;
    if (j >= g_cnt[b*T_ + T_ - 1]) return;
    const int src = g_pos[b*T_ + j];
    const size_t so = (size_t)(b*T_ + src) * C_;
    const size_t dofs = (size_t)(b*T_ + j) * C_;
    ((float4*)(g_xch + dofs))[threadIdx.x] = ((const float4*)(g_xh + so))[threadIdx.x];
}

// ---------------------------------------------------------------------------
// fp16x2 GEMM: 128x128 tile, acc = Ah Wh^T + Ah Wl^T + bias
// 3-stage cp.async ring -> ONE __syncthreads per K-stage.
// ---------------------------------------------------------------------------
__device__ __forceinline__ void tc_gemm_tile(
    const __half* __restrict__ Ah,
    const __half* __restrict__ Wh, const __half* __restrict__ Wl,
    const float* __restrict__ bias,
    float* __restrict__ outF, __half* __restrict__ outH,
    __half* __restrict__ outL, float scale)
{
    const uint32_t sb = smem_to_u32(dyn_smem);

    const int tid  = threadIdx.x;
    const int wid  = tid >> 5;
    const int lane = tid & 31;
    const int g    = lane >> 2;
    const int tig  = lane & 3;

    const int row0 = blockIdx.y * 128;
    const int col0 = blockIdx.x * 128;
    const int warpM = (wid & 1) * 64;
    const int warpN = (wid >> 1) * 32;

    auto issue_chunk = [&](int st, uint32_t stage) {
        const int k0 = st * 32;
        #pragma unroll
        for (int p = 0; p < 2; ++p) {
            const int gid = tid + p * 256;
            const int r = gid >> 2, c = gid & 3;
            const uint32_t d = stage + (uint32_t)(r * PH + c * 8) * 2u;
            const size_t so = (size_t)(row0 + r) * C_ + k0 + c * 8;
            const size_t wo = (size_t)(col0 + r) * C_ + k0 + c * 8;
            cp_async16(d,             Ah + so);
            cp_async16(d + TILEB,     Wh + wo);
            cp_async16(d + 2 * TILEB, Wl + wo);
        }
        CP_COMMIT();
    };

    float acc[4][4][4];
    #pragma unroll
    for (int mf = 0; mf < 4; ++mf)
        #pragma unroll
        for (int nf = 0; nf < 4; ++nf)
            #pragma unroll
            for (int r = 0; r < 4; ++r) acc[mf][nf][r] = 0.f;

    issue_chunk(0, sb);
    issue_chunk(1, sb + STAGEB);

    const int aRow = (lane & 15);
    const int aCol = (lane >> 4) << 3;
    const int bR4  = ((lane >> 4) << 3) + (lane & 7);
    const int bC4  = ((lane >> 3) & 1) << 3;

    int bufc = 0;                       // buffer of stage st  (st % 3)
    int bufn = 2;                       // buffer of stage st+2
    for (int st = 0; st < 32; ++st) {
        if (st < 31) { asm volatile("cp.async.wait_group 1;" ::: "memory"); }
        else         { asm volatile("cp.async.wait_group 0;" ::: "memory"); }
        __syncthreads();   // data from wait visible to all; prior-stage reads done

        if (st + 2 < 32) issue_chunk(st + 2, sb + (uint32_t)bufn * STAGEB);

        const uint32_t stage = sb + (uint32_t)bufc * STAGEB;
        bufc = (bufc == 2) ? 0 : bufc + 1;
        bufn = (bufn == 2) ? 0 : bufn + 1;

        #pragma unroll
        for (int kk = 0; kk < 2; ++kk) {
            const int k16 = kk * 16;

            uint32_t af[4][4];
            #pragma unroll
            for (int mf = 0; mf < 4; ++mf) {
                const uint32_t a = stage +
                    (uint32_t)((warpM + mf * 16 + aRow) * PH + k16 + aCol) * 2u;
                ldmx4(af[mf][0], af[mf][1], af[mf][2], af[mf][3], a);
            }
            uint32_t bh[2][4], bl[2][4];
            #pragma unroll
            for (int np = 0; np < 2; ++np) {
                const uint32_t off =
                    (uint32_t)((warpN + np * 16 + bR4) * PH + k16 + bC4) * 2u;
                ldmx4(bh[np][0], bh[np][1], bh[np][2], bh[np][3],
                      stage + TILEB + off);
                ldmx4(bl[np][0], bl[np][1], bl[np][2], bl[np][3],
                      stage + 2 * TILEB + off);
            }
            #pragma unroll
            for (int mf = 0; mf < 4; ++mf)
                #pragma unroll
                for (int np = 0; np < 2; ++np) {
                    mma_f16(acc[mf][2*np][0], acc[mf][2*np][1],
                            acc[mf][2*np][2], acc[mf][2*np][3],
                            af[mf][0], af[mf][1], af[mf][2], af[mf][3],
                            bh[np][0], bh[np][1]);
                    mma_f16(acc[mf][2*np+1][0], acc[mf][2*np+1][1],
                            acc[mf][2*np+1][2], acc[mf][2*np+1][3],
                            af[mf][0], af[mf][1], af[mf][2], af[mf][3],
                            bh[np][2], bh[np][3]);
                    mma_f16(acc[mf][2*np][0], acc[mf][2*np][1],
                            acc[mf][2*np][2], acc[mf][2*np][3],
                            af[mf][0], af[mf][1], af[mf][2], af[mf][3],
                            bl[np][0], bl[np][1]);
                    mma_f16(acc[mf][2*np+1][0], acc[mf][2*np+1][1],
                            acc[mf][2*np+1][2], acc[mf][2*np+1][3],
                            af[mf][0], af[mf][1], af[mf][2], af[mf][3],
                            bl[np][2], bl[np][3]);
                }
        }
    }

    #pragma unroll
    for (int nf = 0; nf < 4; ++nf) {
        const int colg = col0 + warpN + nf * 8 + tig * 2;
        const float2 bb = *(const float2*)&bias[colg];
        #pragma unroll
        for (int mf = 0; mf < 4; ++mf) {
            const int rowg = row0 + warpM + mf * 16 + g;
            const float v00 = acc[mf][nf][0] + bb.x, v01 = acc[mf][nf][1] + bb.y;
            const float v10 = acc[mf][nf][2] + bb.x, v11 = acc[mf][nf][3] + bb.y;
            if (outF) {
                *(float2*)&outF[(size_t)rowg * C_ + colg]       = make_float2(v00, v01);
                *(float2*)&outF[(size_t)(rowg + 8) * C_ + colg] = make_float2(v10, v11);
            } else if (outL) {
                uint32_t hh, ll;
                pack_hl(v00 * scale, v01 * scale, hh, ll);
                *(uint32_t*)&outH[(size_t)rowg * C_ + colg] = hh;
                *(uint32_t*)&outL[(size_t)rowg * C_ + colg] = ll;
                pack_hl(v10 * scale, v11 * scale, hh, ll);
                *(uint32_t*)&outH[(size_t)(rowg + 8) * C_ + colg] = hh;
                *(uint32_t*)&outL[(size_t)(rowg + 8) * C_ + colg] = ll;
            } else {
                *(uint32_t*)&outH[(size_t)rowg * C_ + colg] =
                    pack_h2(v00 * scale, v01 * scale);
                *(uint32_t*)&outH[(size_t)(rowg + 8) * C_ + colg] =
                    pack_h2(v10 * scale, v11 * scale);
            }
        }
    }
}

// Q scaled by (1/sqrt(D)) * log2(e) so softmax runs in exp2 domain
#define QSCALE (0.125f * 1.4426950408889634f)

__global__ void __launch_bounds__(256, 2) qkv_kernel(
    const float* __restrict__ bq, const float* __restrict__ bk,
    const float* __restrict__ bv)
{
    const int sel = blockIdx.z;
    if (sel != 0) {
        const int row0 = blockIdx.y * 128;
        const int b = row0 / T_;
        const int local = row0 - b * T_;
        if (local >= g_cnt[b*T_ + T_ - 1]) return;
    }
    const __half* Ah   = (sel == 0) ? g_xh  : g_xch;
    const __half* Wh   = (sel == 0) ? g_wqh : (sel == 1) ? g_wkh : g_wvh;
    const __half* Wl   = (sel == 0) ? g_wql : (sel == 1) ? g_wkl : g_wvl;
    const float*  bias = (sel == 0) ? bq    : (sel == 1) ? bk    : bv;
    __half* outH       = (sel == 0) ? g_qh  : (sel == 1) ? g_kch : g_vch;
    __half* outL       = (sel == 0) ? g_ql  : (sel == 1) ? g_kcl : g_vcl;
    const float scale  = (sel == 0) ? QSCALE : 1.0f;
    tc_gemm_tile(Ah, Wh, Wl, bias, nullptr, outH, outL, scale);
}

__global__ void __launch_bounds__(256, 2) proj_kernel(
    const float* __restrict__ bp, float* __restrict__ out)
{
    tc_gemm_tile(g_ah, g_wph, g_wpl, bp, out, nullptr, nullptr, 1.0f);
}

// ---------------------------------------------------------------------------
// fp16x3 flash attention over COMPACTED K/V (unchanged from R12)
// ---------------------------------------------------------------------------
__global__ void __launch_bounds__(256, 2) attn_kernel()
{
    const uint32_t sb = smem_to_u32(dyn_smem);

    const int qt = (T_ / 128 - 1) - blockIdx.x;
    const int h = blockIdx.y, b = blockIdx.z;
    const int q0 = qt * 128;
    const int tid = threadIdx.x, w = tid >> 5, lane = tid & 31;
    const int g = lane >> 2, tig = lane & 3;
    const int rowBase = b * T_;
    const int hc = h * D_;

    #pragma unroll
    for (int it = 0; it < 4; ++it) {
        const int gr = tid + it * 256;
        const int r = gr >> 3, c8 = (gr & 7) * 8;
        const size_t src = (size_t)(rowBase + q0 + r) * C_ + hc + c8;
        const uint32_t d = sb + (uint32_t)(r * PQ + c8) * 2u;
        cp_async16(d + QH_OFF, g_qh + src);
        cp_async16(d + QL_OFF, g_ql + src);
    }

    auto issueKV = [&](int kt, int buf) {
        const int k0 = kt * 64;
        const uint32_t base = sb + ST_OFF + (uint32_t)buf * STAGEA;
        #pragma unroll
        for (int it = 0; it < 2; ++it) {
            const int gr = tid + it * 256;
            const int r = gr >> 3, c8 = (gr & 7) * 8;
            const size_t src = (size_t)(rowBase + k0 + r) * C_ + hc + c8;
            const uint32_t d = base + (uint32_t)(r * PQ + c8) * 2u;
            cp_async16(d,              g_kch + src);
            cp_async16(d + KVTILE,     g_kcl + src);
            cp_async16(d + 2 * KVTILE, g_vch + src);
            cp_async16(d + 3 * KVTILE, g_vcl + src);
        }
        CP_COMMIT();
    };

    issueKV(0, 0);

    const int rA = q0 + w * 16 + g;
    const int rB = rA + 8;
    const int cntA = g_cnt[rowBase + rA];
    const int cntB = g_cnt[rowBase + rB];
    const int NVq  = g_cnt[rowBase + q0 + 127];
    const int nkt  = (NVq + 63) >> 6;

    float o[8][4];
    #pragma unroll
    for (int nf = 0; nf < 8; ++nf)
        #pragma unroll
        for (int c = 0; c < 4; ++c) o[nf][c] = 0.f;
    float mA = -1e30f, mB = -1e30f, lA = 0.f, lB = 0.f;

    const int aRow = lane & 15, aCol = (lane >> 4) << 3;
    const int bR4 = ((lane >> 4) << 3) + (lane & 7);
    const int bC4 = ((lane >> 3) & 1) << 3;
    const int vR  = lane & 15;
    const int vC4 = (lane >> 4) << 3;

    for (int kt = 0; kt < nkt; ++kt) {
        const int buf = kt & 1;
        if (kt + 1 < nkt) {
            issueKV(kt + 1, buf ^ 1);
            asm volatile("cp.async.wait_group 1;" ::: "memory");
        } else {
            asm volatile("cp.async.wait_group 0;" ::: "memory");
        }
        __syncthreads();

        const int k0 = kt * 64;
        const uint32_t KH = sb + ST_OFF + (uint32_t)buf * STAGEA;
        const uint32_t KL = KH + KVTILE;
        const uint32_t VH = KH + 2 * KVTILE;
        const uint32_t VL = KH + 3 * KVTILE;

        float s[8][4];
        #pragma unroll
        for (int nf = 0; nf < 8; ++nf)
            #pragma unroll
            for (int c = 0; c < 4; ++c) s[nf][c] = 0.f;

        #pragma unroll
        for (int kk = 0; kk < 4; ++kk) {
            const int k16 = kk * 16;
            uint32_t aqh[4], aql[4];
            ldmx4(aqh[0], aqh[1], aqh[2], aqh[3],
                  sb + QH_OFF + (uint32_t)((w * 16 + aRow) * PQ + k16 + aCol) * 2u);
            ldmx4(aql[0], aql[1], aql[2], aql[3],
                  sb + QL_OFF + (uint32_t)((w * 16 + aRow) * PQ + k16 + aCol) * 2u);
            #pragma unroll
            for (int np = 0; np < 4; ++np) {
                uint32_t bh[4], bl[4];
                const uint32_t off = (uint32_t)((np * 16 + bR4) * PQ + k16 + bC4) * 2u;
                ldmx4(bh[0], bh[1], bh[2], bh[3], KH + off);
                ldmx4(bl[0], bl[1], bl[2], bl[3], KL + off);
                mma_f16(s[2*np][0], s[2*np][1], s[2*np][2], s[2*np][3],
                        aqh[0], aqh[1], aqh[2], aqh[3], bh[0], bh[1]);
                mma_f16(s[2*np][0], s[2*np][1], s[2*np][2], s[2*np][3],
                        aqh[0], aqh[1], aqh[2], aqh[3], bl[0], bl[1]);
                mma_f16(s[2*np][0], s[2*np][1], s[2*np][2], s[2*np][3],
                        aql[0], aql[1], aql[2], aql[3], bh[0], bh[1]);
                mma_f16(s[2*np+1][0], s[2*np+1][1], s[2*np+1][2], s[2*np+1][3],
                        aqh[0], aqh[1], aqh[2], aqh[3], bh[2], bh[3]);
                mma_f16(s[2*np+1][0], s[2*np+1][1], s[2*np+1][2], s[2*np+1][3],
                        aqh[0], aqh[1], aqh[2], aqh[3], bl[2], bl[3]);
                mma_f16(s[2*np+1][0], s[2*np+1][1], s[2*np+1][2], s[2*np+1][3],
                        aql[0], aql[1], aql[2], aql[3], bh[2], bh[3]);
            }
        }

        #pragma unroll
        for (int nf = 0; nf < 8; ++nf) {
            const int c0 = k0 + nf * 8 + tig * 2;
            s[nf][0] = (c0     < cntA) ? s[nf][0] : -1e30f;
            s[nf][1] = (c0 + 1 < cntA) ? s[nf][1] : -1e30f;
            s[nf][2] = (c0     < cntB) ? s[nf][2] : -1e30f;
            s[nf][3] = (c0 + 1 < cntB) ? s[nf][3] : -1e30f;
        }

        float mxA = -1e30f, mxB = -1e30f;
        #pragma unroll
        for (int nf = 0; nf < 8; ++nf) {
            mxA = fmaxf(mxA, fmaxf(s[nf][0], s[nf][1]));
            mxB = fmaxf(mxB, fmaxf(s[nf][2], s[nf][3]));
        }
        mxA = fmaxf(mxA, __shfl_xor_sync(0xffffffffu, mxA, 1));
        mxA = fmaxf(mxA, __shfl_xor_sync(0xffffffffu, mxA, 2));
        mxB = fmaxf(mxB, __shfl_xor_sync(0xffffffffu, mxB, 1));
        mxB = fmaxf(mxB, __shfl_xor_sync(0xffffffffu, mxB, 2));
        const float mnA = fmaxf(mA, mxA), mnB = fmaxf(mB, mxB);
        const float cA = ex2f(mA - mnA), cB = ex2f(mB - mnB);
        mA = mnA; mB = mnB;
        float sA = 0.f, sB = 0.f;
        #pragma unroll
        for (int nf = 0; nf < 8; ++nf) {
            s[nf][0] = ex2f(s[nf][0] - mnA);
            s[nf][1] = ex2f(s[nf][1] - mnA);
            s[nf][2] = ex2f(s[nf][2] - mnB);
            s[nf][3] = ex2f(s[nf][3] - mnB);
            sA += s[nf][0] + s[nf][1];
            sB += s[nf][2] + s[nf][3];
        }
        sA += __shfl_xor_sync(0xffffffffu, sA, 1);
        sA += __shfl_xor_sync(0xffffffffu, sA, 2);
        sB += __shfl_xor_sync(0xffffffffu, sB, 1);
        sB += __shfl_xor_sync(0xffffffffu, sB, 2);
        lA = lA * cA + sA;
        lB = lB * cB + sB;
        #pragma unroll
        for (int nf = 0; nf < 8; ++nf) {
            o[nf][0] *= cA; o[nf][1] *= cA;
            o[nf][2] *= cB; o[nf][3] *= cB;
        }

        #pragma unroll
        for (int j = 0; j < 4; ++j) {
            uint32_t ph[4];
            ph[0] = pack_h2(s[2*j][0],   s[2*j][1]);
            ph[1] = pack_h2(s[2*j][2],   s[2*j][3]);
            ph[2] = pack_h2(s[2*j+1][0], s[2*j+1][1]);
            ph[3] = pack_h2(s[2*j+1][2], s[2*j+1][3]);
            #pragma unroll
            for (int np = 0; np < 4; ++np) {
                uint32_t bh[4], bl[4];
                const uint32_t off = (uint32_t)((j * 16 + vR) * PQ + np * 16 + vC4) * 2u;
                ldmx4t(bh[0], bh[1], bh[2], bh[3], VH + off);
                ldmx4t(bl[0], bl[1], bl[2], bl[3], VL + off);
                mma_f16(o[2*np][0], o[2*np][1], o[2*np][2], o[2*np][3],
                        ph[0], ph[1], ph[2], ph[3], bh[0], bh[1]);
                mma_f16(o[2*np][0], o[2*np][1], o[2*np][2], o[2*np][3],
                        ph[0], ph[1], ph[2], ph[3], bl[0], bl[1]);
                mma_f16(o[2*np+1][0], o[2*np+1][1], o[2*np+1][2], o[2*np+1][3],
                        ph[0], ph[1], ph[2], ph[3], bh[2], bh[3]);
                mma_f16(o[2*np+1][0], o[2*np+1][1], o[2*np+1][2], o[2*np+1][3],
                        ph[0], ph[1], ph[2], ph[3], bl[2], bl[3]);
            }
        }
        __syncthreads();
    }

    const float invA = 1.f / lA, invB = 1.f / lB;
    #pragma unroll
    for (int nf = 0; nf < 8; ++nf) {
        const int col = hc + nf * 8 + tig * 2;
        const size_t iA = (size_t)(rowBase + rA) * C_ + col;
        const size_t iB = iA + (size_t)8 * C_;
        *(uint32_t*)&g_ah[iA] = pack_h2(o[nf][0] * invA, o[nf][1] * invA);
        *(uint32_t*)&g_ah[iB] = pack_h2(o[nf][2] * invB, o[nf][3] * invB);
    }
}

// ---------------------------------------------------------------------------
// Launch
// ---------------------------------------------------------------------------
extern "C" void kernel_launch(void* const* d_in, const int* in_sizes, int n_in,
                              void* d_out, int out_size)
{
    const float* x  = (const float*)d_in[0];
    const int*   tm = (const int*)  d_in[1];
    const float* wq = (const float*)d_in[2];
    const float* bq = (const float*)d_in[3];
    const float* wk = (const float*)d_in[4];
    const float* bk = (const float*)d_in[5];
    const float* wv = (const float*)d_in[6];
    const float* bv = (const float*)d_in[7];
    const float* wp = (const float*)d_in[8];
    const float* bp = (const float*)d_in[9];
    float* out = (float*)d_out;

    cudaFuncSetAttribute(qkv_kernel,  cudaFuncAttributeMaxDynamicSharedMemorySize, GSMEM);
    cudaFuncSetAttribute(proj_kernel, cudaFuncAttributeMaxDynamicSharedMemorySize, GSMEM);
    cudaFuncSetAttribute(attn_kernel, cudaFuncAttributeMaxDynamicSharedMemorySize, ATT_SMEM);

    const int nTot = (NX + 4 * NW) / 1024;
    split_all_kernel<<<nTot, 256>>>(x, wq, wk, wv, wp);
    mask_scan_kernel<<<B_, 256>>>(tm);

    dim3 gGx(T_, B_);
    gather_x_kernel<<<gGx, 128>>>();

    dim3 gQKV(C_/128, M_/128, 3);
    qkv_kernel<<<gQKV, 256, GSMEM>>>(bq, bk, bv);

    dim3 gAtt(T_/128, NH_, B_);
    attn_kernel<<<gAtt, 256, ATT_SMEM>>>();

    dim3 gProj(C_/128, M_/128, 1);
    proj_kernel<<<gProj, 256, GSMEM>>>(bp, out);
}

// round 15
// speedup vs baseline: 1.3361x; 1.3361x over previous
#include <cuda_runtime.h>
#include <cuda_fp16.h>
#include <cstdint>

#define B_  4
#define T_  2048
#define C_  1024
#define NH_ 16
#define D_  64
#define M_  (B_*T_)
#define NX  (M_*C_)
#define NW  (C_*C_)

// ---- GEMM smem (halves, pitch 40): 2 tiles/stage (Ah, Wh), 3 stages ----
#define PH     40
#define TILEB  10240u
#define STAGEB 20480u
#define GSMEM  61440

// ---- Attention smem: Q(h,l) 128x64 + 2 stages x (Kh,Kl,Vh,Vl) 64x64 ----
#define PQ 72
#define KVTILE 9216u               // 64*PQ*2
#define STAGEA 36864u              // 4 KV tiles
#define QH_OFF 0u
#define QL_OFF 18432u
#define ST_OFF 36864u
#define ATT_SMEM 110592

extern __shared__ char dyn_smem[];

// Scratch (static device globals — no allocation at runtime)
__device__ __half g_qh[M_*C_],  g_ql[M_*C_];
__device__ __half g_ah[M_*C_];                  // attention out (hi only)
__device__ __half g_xh[M_*C_];                  // x hi
__device__ __half g_xch[M_*C_];                 // compacted x hi
__device__ __half g_wqh[C_*C_];
__device__ __half g_wkh[C_*C_];
__device__ __half g_wvh[C_*C_];
__device__ __half g_wph[C_*C_];
// mask compaction
__device__ int    g_cnt[B_*T_];
__device__ int    g_pos[B_*T_];
// compacted K/V (written directly by K/V GEMM epilogue; lo from fp32 acc)
__device__ __half g_kch[M_*C_], g_kcl[M_*C_];
__device__ __half g_vch[M_*C_], g_vcl[M_*C_];

// ---------------------------------------------------------------------------
// helpers
// ---------------------------------------------------------------------------
__device__ __forceinline__ uint32_t smem_to_u32(const void* p) {
    uint32_t a;
    asm("{ .reg .u64 t; cvta.to.shared.u64 t, %1; cvt.u32.u64 %0, t; }"
        : "=r"(a) : "l"(p));
    return a;
}

__device__ __forceinline__ void cp_async16(uint32_t s, const void* g) {
    asm volatile("cp.async.cg.shared.global [%0], [%1], 16;" :: "r"(s), "l"(g));
}
#define CP_COMMIT() asm volatile("cp.async.commit_group;" ::: "memory")

__device__ __forceinline__ void ldmx4(uint32_t& r0, uint32_t& r1,
                                      uint32_t& r2, uint32_t& r3, uint32_t a) {
    asm volatile("ldmatrix.sync.aligned.m8n8.x4.shared.b16 {%0,%1,%2,%3}, [%4];"
                 : "=r"(r0), "=r"(r1), "=r"(r2), "=r"(r3) : "r"(a));
}
__device__ __forceinline__ void ldmx4t(uint32_t& r0, uint32_t& r1,
                                       uint32_t& r2, uint32_t& r3, uint32_t a) {
    asm volatile("ldmatrix.sync.aligned.m8n8.x4.trans.shared.b16 {%0,%1,%2,%3}, [%4];"
                 : "=r"(r0), "=r"(r1), "=r"(r2), "=r"(r3) : "r"(a));
}

__device__ __forceinline__ void mma_f16(float& c0, float& c1, float& c2, float& c3,
                                        uint32_t a0, uint32_t a1, uint32_t a2, uint32_t a3,
                                        uint32_t b0, uint32_t b1) {
    asm volatile(
        "mma.sync.aligned.m16n8k16.row.col.f32.f16.f16.f32 "
        "{%0,%1,%2,%3}, {%4,%5,%6,%7}, {%8,%9}, {%0,%1,%2,%3};\n"
        : "+f"(c0), "+f"(c1), "+f"(c2), "+f"(c3)
        : "r"(a0), "r"(a1), "r"(a2), "r"(a3), "r"(b0), "r"(b1));
}

__device__ __forceinline__ float ex2f(float x) {
    float r;
    asm("ex2.approx.f32 %0, %1;" : "=f"(r) : "f"(x));
    return r;
}

__device__ __forceinline__ uint32_t pack_h2(float x, float y) {
    uint32_t r;
    asm("cvt.rn.f16x2.f32 %0, %1, %2;" : "=r"(r) : "f"(y), "f"(x));
    return r;
}

__device__ __forceinline__ void pack_hl(float x, float y, uint32_t& hh, uint32_t& ll) {
    __half hx = __float2half_rn(x), hy = __float2half_rn(y);
    __half lx = __float2half_rn(x - __half2float(hx));
    __half ly = __float2half_rn(y - __half2float(hy));
    __half2 H = __halves2half2(hx, hy), L = __halves2half2(lx, ly);
    hh = *(uint32_t*)&H; ll = *(uint32_t*)&L;
}

// ---------------------------------------------------------------------------
// fused split prepass: x and all weights -> fp16 hi only
// ---------------------------------------------------------------------------
__global__ void __launch_bounds__(256) split_all_kernel(
    const float* __restrict__ x,  const float* __restrict__ wq,
    const float* __restrict__ wk, const float* __restrict__ wv,
    const float* __restrict__ wp)
{
    const long long i4 = ((long long)blockIdx.x * 256 + threadIdx.x) * 4;
    const float* src; __half* dh; long long off;
    if (i4 < (long long)NX) {
        src = x; dh = g_xh; off = i4;
    } else {
        const long long r = i4 - (long long)NX;
        const int wsel = (int)(r >> 20);          // NW == 1<<20
        off = r & (long long)(NW - 1);
        switch (wsel) {
            case 0:  src = wq; dh = g_wqh; break;
            case 1:  src = wk; dh = g_wkh; break;
            case 2:  src = wv; dh = g_wvh; break;
            default: src = wp; dh = g_wph; break;
        }
    }
    float4 v = *(const float4*)(src + off);
    *(uint32_t*)(dh + off)     = pack_h2(v.x, v.y);
    *(uint32_t*)(dh + off + 2) = pack_h2(v.z, v.w);
}

// ---------------------------------------------------------------------------
// token-mask scan: per batch, inclusive counts + compact position list
// ---------------------------------------------------------------------------
__global__ void __launch_bounds__(256) mask_scan_kernel(const int* __restrict__ tmask)
{
    __shared__ int wsum[8];
    const int b = blockIdx.x;
    const int tid = threadIdx.x;
    const int lane = tid & 31, wid = tid >> 5;
    const int t0 = tid * 8;

    int v[8]; int s = 0;
    #pragma unroll
    for (int i = 0; i < 8; ++i) { v[i] = (tmask[b*T_ + t0 + i] != 0) ? 1 : 0; s += v[i]; }

    int sc = s;
    #pragma unroll
    for (int off = 1; off < 32; off <<= 1) {
        int n = __shfl_up_sync(0xffffffffu, sc, off);
        if (lane >= off) sc += n;
    }
    if (lane == 31) wsum[wid] = sc;
    __syncthreads();
    if (tid == 0) {
        int acc = 0;
        #pragma unroll
        for (int i = 0; i < 8; ++i) { acc += wsum[i]; wsum[i] = acc; }
    }
    __syncthreads();
    const int wbase = (wid > 0) ? wsum[wid - 1] : 0;
    int run = wbase + sc - s;
    #pragma unroll
    for (int i = 0; i < 8; ++i) {
        run += v[i];
        g_cnt[b*T_ + t0 + i] = run;
        if (v[i]) g_pos[b*T_ + run - 1] = t0 + i;
    }
}

// ---------------------------------------------------------------------------
// gather valid x rows (hi) into compacted buffer
// ---------------------------------------------------------------------------
__global__ void __launch_bounds__(128) gather_x_kernel()
{
    const int j = blockIdx.x, b = blockIdx.y;
    if (j >= g_cnt[b*T_ + T_ - 1]) return;
    const int src = g_pos[b*T_ + j];
    const size_t so = (size_t)(b*T_ + src) * C_;
    const size_t dofs = (size_t)(b*T_ + j) * C_;
    ((float4*)(g_xch + dofs))[threadIdx.x] = ((const float4*)(g_xh + so))[threadIdx.x];
}

// ---------------------------------------------------------------------------
// plain fp16 GEMM (fp32 acc): 128x128 tile, acc = Ah Wh^T + bias
// 3-stage cp.async ring, one __syncthreads per K-stage.
// ---------------------------------------------------------------------------
__device__ __forceinline__ void tc_gemm_tile(
    const __half* __restrict__ Ah, const __half* __restrict__ Wh,
    const float* __restrict__ bias,
    float* __restrict__ outF, __half* __restrict__ outH,
    __half* __restrict__ outL, float scale)
{
    const uint32_t sb = smem_to_u32(dyn_smem);

    const int tid  = threadIdx.x;
    const int wid  = tid >> 5;
    const int lane = tid & 31;
    const int g    = lane >> 2;
    const int tig  = lane & 3;

    const int row0 = blockIdx.y * 128;
    const int col0 = blockIdx.x * 128;
    const int warpM = (wid & 1) * 64;
    const int warpN = (wid >> 1) * 32;

    auto issue_chunk = [&](int st, uint32_t stage) {
        const int k0 = st * 32;
        #pragma unroll
        for (int p = 0; p < 2; ++p) {
            const int gid = tid + p * 256;
            const int r = gid >> 2, c = gid & 3;
            const uint32_t d = stage + (uint32_t)(r * PH + c * 8) * 2u;
            cp_async16(d,         Ah + (size_t)(row0 + r) * C_ + k0 + c * 8);
            cp_async16(d + TILEB, Wh + (size_t)(col0 + r) * C_ + k0 + c * 8);
        }
        CP_COMMIT();
    };

    float acc[4][4][4];
    #pragma unroll
    for (int mf = 0; mf < 4; ++mf)
        #pragma unroll
        for (int nf = 0; nf < 4; ++nf)
            #pragma unroll
            for (int r = 0; r < 4; ++r) acc[mf][nf][r] = 0.f;

    issue_chunk(0, sb);
    issue_chunk(1, sb + STAGEB);

    const int aRow = (lane & 15);
    const int aCol = (lane >> 4) << 3;
    const int bR4  = ((lane >> 4) << 3) + (lane & 7);
    const int bC4  = ((lane >> 3) & 1) << 3;

    int bufc = 0;
    int bufn = 2;
    for (int st = 0; st < 32; ++st) {
        if (st < 31) { asm volatile("cp.async.wait_group 1;" ::: "memory"); }
        else         { asm volatile("cp.async.wait_group 0;" ::: "memory"); }
        __syncthreads();

        if (st + 2 < 32) issue_chunk(st + 2, sb + (uint32_t)bufn * STAGEB);

        const uint32_t stage = sb + (uint32_t)bufc * STAGEB;
        bufc = (bufc == 2) ? 0 : bufc + 1;
        bufn = (bufn == 2) ? 0 : bufn + 1;

        #pragma unroll
        for (int kk = 0; kk < 2; ++kk) {
            const int k16 = kk * 16;

            uint32_t af[4][4];
            #pragma unroll
            for (int mf = 0; mf < 4; ++mf) {
                const uint32_t a = stage +
                    (uint32_t)((warpM + mf * 16 + aRow) * PH + k16 + aCol) * 2u;
                ldmx4(af[mf][0], af[mf][1], af[mf][2], af[mf][3], a);
            }
            uint32_t bh[2][4];
            #pragma unroll
            for (int np = 0; np < 2; ++np) {
                const uint32_t off =
                    (uint32_t)((warpN + np * 16 + bR4) * PH + k16 + bC4) * 2u;
                ldmx4(bh[np][0], bh[np][1], bh[np][2], bh[np][3],
                      stage + TILEB + off);
            }
            #pragma unroll
            for (int mf = 0; mf < 4; ++mf)
                #pragma unroll
                for (int np = 0; np < 2; ++np) {
                    mma_f16(acc[mf][2*np][0], acc[mf][2*np][1],
                            acc[mf][2*np][2], acc[mf][2*np][3],
                            af[mf][0], af[mf][1], af[mf][2], af[mf][3],
                            bh[np][0], bh[np][1]);
                    mma_f16(acc[mf][2*np+1][0], acc[mf][2*np+1][1],
                            acc[mf][2*np+1][2], acc[mf][2*np+1][3],
                            af[mf][0], af[mf][1], af[mf][2], af[mf][3],
                            bh[np][2], bh[np][3]);
                }
        }
    }

    #pragma unroll
    for (int nf = 0; nf < 4; ++nf) {
        const int colg = col0 + warpN + nf * 8 + tig * 2;
        const float2 bb = *(const float2*)&bias[colg];
        #pragma unroll
        for (int mf = 0; mf < 4; ++mf) {
            const int rowg = row0 + warpM + mf * 16 + g;
            const float v00 = acc[mf][nf][0] + bb.x, v01 = acc[mf][nf][1] + bb.y;
            const float v10 = acc[mf][nf][2] + bb.x, v11 = acc[mf][nf][3] + bb.y;
            if (outF) {
                *(float2*)&outF[(size_t)rowg * C_ + colg]       = make_float2(v00, v01);
                *(float2*)&outF[(size_t)(rowg + 8) * C_ + colg] = make_float2(v10, v11);
            } else if (outL) {
                uint32_t hh, ll;
                pack_hl(v00 * scale, v01 * scale, hh, ll);
                *(uint32_t*)&outH[(size_t)rowg * C_ + colg] = hh;
                *(uint32_t*)&outL[(size_t)rowg * C_ + colg] = ll;
                pack_hl(v10 * scale, v11 * scale, hh, ll);
                *(uint32_t*)&outH[(size_t)(rowg + 8) * C_ + colg] = hh;
                *(uint32_t*)&outL[(size_t)(rowg + 8) * C_ + colg] = ll;
            } else {
                *(uint32_t*)&outH[(size_t)rowg * C_ + colg] =
                    pack_h2(v00 * scale, v01 * scale);
                *(uint32_t*)&outH[(size_t)(rowg + 8) * C_ + colg] =
                    pack_h2(v10 * scale, v11 * scale);
            }
        }
    }
}

// Q scaled by (1/sqrt(D)) * log2(e) so softmax runs in exp2 domain
#define QSCALE (0.125f * 1.4426950408889634f)

__global__ void __launch_bounds__(256, 2) qkv_kernel(
    const float* __restrict__ bq, const float* __restrict__ bk,
    const float* __restrict__ bv)
{
    const int sel = blockIdx.z;
    if (sel != 0) {
        const int row0 = blockIdx.y * 128;
        const int b = row0 / T_;
        const int local = row0 - b * T_;
        if (local >= g_cnt[b*T_ + T_ - 1]) return;
    }
    const __half* Ah   = (sel == 0) ? g_xh  : g_xch;
    const __half* Wh   = (sel == 0) ? g_wqh : (sel == 1) ? g_wkh : g_wvh;
    const float*  bias = (sel == 0) ? bq    : (sel == 1) ? bk    : bv;
    __half* outH       = (sel == 0) ? g_qh  : (sel == 1) ? g_kch : g_vch;
    __half* outL       = (sel == 0) ? g_ql  : (sel == 1) ? g_kcl : g_vcl;
    const float scale  = (sel == 0) ? QSCALE : 1.0f;
    tc_gemm_tile(Ah, Wh, bias, nullptr, outH, outL, scale);
}

__global__ void __launch_bounds__(256, 2) proj_kernel(
    const float* __restrict__ bp, float* __restrict__ out)
{
    tc_gemm_tile(g_ah, g_wph, bp, out, nullptr, nullptr, 1.0f);
}

// ---------------------------------------------------------------------------
// fp16x3 flash attention over COMPACTED K/V (unchanged)
// ---------------------------------------------------------------------------
__global__ void __launch_bounds__(256, 2) attn_kernel()
{
    const uint32_t sb = smem_to_u32(dyn_smem);

    const int qt = (T_ / 128 - 1) - blockIdx.x;
    const int h = blockIdx.y, b = blockIdx.z;
    const int q0 = qt * 128;
    const int tid = threadIdx.x, w = tid >> 5, lane = tid & 31;
    const int g = lane >> 2, tig = lane & 3;
    const int rowBase = b * T_;
    const int hc = h * D_;

    #pragma unroll
    for (int it = 0; it < 4; ++it) {
        const int gr = tid + it * 256;
        const int r = gr >> 3, c8 = (gr & 7) * 8;
        const size_t src = (size_t)(rowBase + q0 + r) * C_ + hc + c8;
        const uint32_t d = sb + (uint32_t)(r * PQ + c8) * 2u;
        cp_async16(d + QH_OFF, g_qh + src);
        cp_async16(d + QL_OFF, g_ql + src);
    }

    auto issueKV = [&](int kt, int buf) {
        const int k0 = kt * 64;
        const uint32_t base = sb + ST_OFF + (uint32_t)buf * STAGEA;
        #pragma unroll
        for (int it = 0; it < 2; ++it) {
            const int gr = tid + it * 256;
            const int r = gr >> 3, c8 = (gr & 7) * 8;
            const size_t src = (size_t)(rowBase + k0 + r) * C_ + hc + c8;
            const uint32_t d = base + (uint32_t)(r * PQ + c8) * 2u;
            cp_async16(d,              g_kch + src);
            cp_async16(d + KVTILE,     g_kcl + src);
            cp_async16(d + 2 * KVTILE, g_vch + src);
            cp_async16(d + 3 * KVTILE, g_vcl + src);
        }
        CP_COMMIT();
    };

    issueKV(0, 0);

    const int rA = q0 + w * 16 + g;
    const int rB = rA + 8;
    const int cntA = g_cnt[rowBase + rA];
    const int cntB = g_cnt[rowBase + rB];
    const int NVq  = g_cnt[rowBase + q0 + 127];
    const int nkt  = (NVq + 63) >> 6;

    float o[8][4];
    #pragma unroll
    for (int nf = 0; nf < 8; ++nf)
        #pragma unroll
        for (int c = 0; c < 4; ++c) o[nf][c] = 0.f;
    float mA = -1e30f, mB = -1e30f, lA = 0.f, lB = 0.f;

    const int aRow = lane & 15, aCol = (lane >> 4) << 3;
    const int bR4 = ((lane >> 4) << 3) + (lane & 7);
    const int bC4 = ((lane >> 3) & 1) << 3;
    const int vR  = lane & 15;
    const int vC4 = (lane >> 4) << 3;

    for (int kt = 0; kt < nkt; ++kt) {
        const int buf = kt & 1;
        if (kt + 1 < nkt) {
            issueKV(kt + 1, buf ^ 1);
            asm volatile("cp.async.wait_group 1;" ::: "memory");
        } else {
            asm volatile("cp.async.wait_group 0;" ::: "memory");
        }
        __syncthreads();

        const int k0 = kt * 64;
        const uint32_t KH = sb + ST_OFF + (uint32_t)buf * STAGEA;
        const uint32_t KL = KH + KVTILE;
        const uint32_t VH = KH + 2 * KVTILE;
        const uint32_t VL = KH + 3 * KVTILE;

        float s[8][4];
        #pragma unroll
        for (int nf = 0; nf < 8; ++nf)
            #pragma unroll
            for (int c = 0; c < 4; ++c) s[nf][c] = 0.f;

        #pragma unroll
        for (int kk = 0; kk < 4; ++kk) {
            const int k16 = kk * 16;
            uint32_t aqh[4], aql[4];
            ldmx4(aqh[0], aqh[1], aqh[2], aqh[3],
                  sb + QH_OFF + (uint32_t)((w * 16 + aRow) * PQ + k16 + aCol) * 2u);
            ldmx4(aql[0], aql[1], aql[2], aql[3],
                  sb + QL_OFF + (uint32_t)((w * 16 + aRow) * PQ + k16 + aCol) * 2u);
            #pragma unroll
            for (int np = 0; np < 4; ++np) {
                uint32_t bh[4], bl[4];
                const uint32_t off = (uint32_t)((np * 16 + bR4) * PQ + k16 + bC4) * 2u;
                ldmx4(bh[0], bh[1], bh[2], bh[3], KH + off);
                ldmx4(bl[0], bl[1], bl[2], bl[3], KL + off);
                mma_f16(s[2*np][0], s[2*np][1], s[2*np][2], s[2*np][3],
                        aqh[0], aqh[1], aqh[2], aqh[3], bh[0], bh[1]);
                mma_f16(s[2*np][0], s[2*np][1], s[2*np][2], s[2*np][3],
                        aqh[0], aqh[1], aqh[2], aqh[3], bl[0], bl[1]);
                mma_f16(s[2*np][0], s[2*np][1], s[2*np][2], s[2*np][3],
                        aql[0], aql[1], aql[2], aql[3], bh[0], bh[1]);
                mma_f16(s[2*np+1][0], s[2*np+1][1], s[2*np+1][2], s[2*np+1][3],
                        aqh[0], aqh[1], aqh[2], aqh[3], bh[2], bh[3]);
                mma_f16(s[2*np+1][0], s[2*np+1][1], s[2*np+1][2], s[2*np+1][3],
                        aqh[0], aqh[1], aqh[2], aqh[3], bl[2], bl[3]);
                mma_f16(s[2*np+1][0], s[2*np+1][1], s[2*np+1][2], s[2*np+1][3],
                        aql[0], aql[1], aql[2], aql[3], bh[2], bh[3]);
            }
        }

        #pragma unroll
        for (int nf = 0; nf < 8; ++nf) {
            const int c0 = k0 + nf * 8 + tig * 2;
            s[nf][0] = (c0     < cntA) ? s[nf][0] : -1e30f;
            s[nf][1] = (c0 + 1 < cntA) ? s[nf][1] : -1e30f;
            s[nf][2] = (c0     < cntB) ? s[nf][2] : -1e30f;
            s[nf][3] = (c0 + 1 < cntB) ? s[nf][3] : -1e30f;
        }

        float mxA = -1e30f, mxB = -1e30f;
        #pragma unroll
        for (int nf = 0; nf < 8; ++nf) {
            mxA = fmaxf(mxA, fmaxf(s[nf][0], s[nf][1]));
            mxB = fmaxf(mxB, fmaxf(s[nf][2], s[nf][3]));
        }
        mxA = fmaxf(mxA, __shfl_xor_sync(0xffffffffu, mxA, 1));
        mxA = fmaxf(mxA, __shfl_xor_sync(0xffffffffu, mxA, 2));
        mxB = fmaxf(mxB, __shfl_xor_sync(0xffffffffu, mxB, 1));
        mxB = fmaxf(mxB, __shfl_xor_sync(0xffffffffu, mxB, 2));
        const float mnA = fmaxf(mA, mxA), mnB = fmaxf(mB, mxB);
        const float cA = ex2f(mA - mnA), cB = ex2f(mB - mnB);
        mA = mnA; mB = mnB;
        float sA = 0.f, sB = 0.f;
        #pragma unroll
        for (int nf = 0; nf < 8; ++nf) {
            s[nf][0] = ex2f(s[nf][0] - mnA);
            s[nf][1] = ex2f(s[nf][1] - mnA);
            s[nf][2] = ex2f(s[nf][2] - mnB);
            s[nf][3] = ex2f(s[nf][3] - mnB);
            sA += s[nf][0] + s[nf][1];
            sB += s[nf][2] + s[nf][3];
        }
        sA += __shfl_xor_sync(0xffffffffu, sA, 1);
        sA += __shfl_xor_sync(0xffffffffu, sA, 2);
        sB += __shfl_xor_sync(0xffffffffu, sB, 1);
        sB += __shfl_xor_sync(0xffffffffu, sB, 2);
        lA = lA * cA + sA;
        lB = lB * cB + sB;
        #pragma unroll
        for (int nf = 0; nf < 8; ++nf) {
            o[nf][0] *= cA; o[nf][1] *= cA;
            o[nf][2] *= cB; o[nf][3] *= cB;
        }

        #pragma unroll
        for (int j = 0; j < 4; ++j) {
            uint32_t ph[4];
            ph[0] = pack_h2(s[2*j][0],   s[2*j][1]);
            ph[1] = pack_h2(s[2*j][2],   s[2*j][3]);
            ph[2] = pack_h2(s[2*j+1][0], s[2*j+1][1]);
            ph[3] = pack_h2(s[2*j+1][2], s[2*j+1][3]);
            #pragma unroll
            for (int np = 0; np < 4; ++np) {
                uint32_t bh[4], bl[4];
                const uint32_t off = (uint32_t)((j * 16 + vR) * PQ + np * 16 + vC4) * 2u;
                ldmx4t(bh[0], bh[1], bh[2], bh[3], VH + off);
                ldmx4t(bl[0], bl[1], bl[2], bl[3], VL + off);
                mma_f16(o[2*np][0], o[2*np][1], o[2*np][2], o[2*np][3],
                        ph[0], ph[1], ph[2], ph[3], bh[0], bh[1]);
                mma_f16(o[2*np][0], o[2*np][1], o[2*np][2], o[2*np][3],
                        ph[0], ph[1], ph[2], ph[3], bl[0], bl[1]);
                mma_f16(o[2*np+1][0], o[2*np+1][1], o[2*np+1][2], o[2*np+1][3],
                        ph[0], ph[1], ph[2], ph[3], bh[2], bh[3]);
                mma_f16(o[2*np+1][0], o[2*np+1][1], o[2*np+1][2], o[2*np+1][3],
                        ph[0], ph[1], ph[2], ph[3], bl[2], bl[3]);
            }
        }
        __syncthreads();
    }

    const float invA = 1.f / lA, invB = 1.f / lB;
    #pragma unroll
    for (int nf = 0; nf < 8; ++nf) {
        const int col = hc + nf * 8 + tig * 2;
        const size_t iA = (size_t)(rowBase + rA) * C_ + col;
        const size_t iB = iA + (size_t)8 * C_;
        *(uint32_t*)&g_ah[iA] = pack_h2(o[nf][0] * invA, o[nf][1] * invA);
        *(uint32_t*)&g_ah[iB] = pack_h2(o[nf][2] * invB, o[nf][3] * invB);
    }
}

// ---------------------------------------------------------------------------
// Launch
// ---------------------------------------------------------------------------
extern "C" void kernel_launch(void* const* d_in, const int* in_sizes, int n_in,
                              void* d_out, int out_size)
{
    const float* x  = (const float*)d_in[0];
    const int*   tm = (const int*)  d_in[1];
    const float* wq = (const float*)d_in[2];
    const float* bq = (const float*)d_in[3];
    const float* wk = (const float*)d_in[4];
    const float* bk = (const float*)d_in[5];
    const float* wv = (const float*)d_in[6];
    const float* bv = (const float*)d_in[7];
    const float* wp = (const float*)d_in[8];
    const float* bp = (const float*)d_in[9];
    float* out = (float*)d_out;

    cudaFuncSetAttribute(qkv_kernel,  cudaFuncAttributeMaxDynamicSharedMemorySize, GSMEM);
    cudaFuncSetAttribute(proj_kernel, cudaFuncAttributeMaxDynamicSharedMemorySize, GSMEM);
    cudaFuncSetAttribute(attn_kernel, cudaFuncAttributeMaxDynamicSharedMemorySize, ATT_SMEM);

    const int nTot = (NX + 4 * NW) / 1024;
    split_all_kernel<<<nTot, 256>>>(x, wq, wk, wv, wp);
    mask_scan_kernel<<<B_, 256>>>(tm);

    dim3 gGx(T_, B_);
    gather_x_kernel<<<gGx, 128>>>();

    dim3 gQKV(C_/128, M_/128, 3);
    qkv_kernel<<<gQKV, 256, GSMEM>>>(bq, bk, bv);

    dim3 gAtt(T_/128, NH_, B_);
    attn_kernel<<<gAtt, 256, ATT_SMEM>>>();

    dim3 gProj(C_/128, M_/128, 1);
    proj_kernel<<<gProj, 256, GSMEM>>>(bp, out);
}

// round 16
// speedup vs baseline: 1.5410x; 1.1533x over previous
#include <cuda_runtime.h>
#include <cuda_fp16.h>
#include <cstdint>

#define B_  4
#define T_  2048
#define C_  1024
#define NH_ 16
#define D_  64
#define M_  (B_*T_)
#define NX  (M_*C_)
#define NW  (C_*C_)

// ---- GEMM smem (halves, pitch 40): 2 tiles/stage (Ah, Wh), 3 stages ----
#define PH     40
#define TILEB  10240u
#define STAGEB 20480u
#define GSMEM  61440

// ---- Attention smem: Qh 128x64 + 2 stages x (Kh,Kl,Vh) 64x64 ----
#define PQ 72
#define KVTILE 9216u               // 64*PQ*2
#define STAGEA 27648u              // 3 KV tiles
#define QH_OFF 0u
#define ST_OFF 18432u
#define ATT_SMEM 73728

extern __shared__ char dyn_smem[];

// Scratch (static device globals — no allocation at runtime)
__device__ __half g_qh[M_*C_];
__device__ __half g_ah[M_*C_];                  // attention out (hi only)
__device__ __half g_xh[M_*C_];                  // x hi
__device__ __half g_xch[M_*C_];                 // compacted x hi
__device__ __half g_wqh[C_*C_];
__device__ __half g_wkh[C_*C_];
__device__ __half g_wvh[C_*C_];
__device__ __half g_wph[C_*C_];
// mask compaction
__device__ int    g_cnt[B_*T_];
__device__ int    g_pos[B_*T_];
// compacted K (hi+lo from fp32 acc) and V (hi only)
__device__ __half g_kch[M_*C_], g_kcl[M_*C_];
__device__ __half g_vch[M_*C_];

// ---------------------------------------------------------------------------
// helpers
// ---------------------------------------------------------------------------
__device__ __forceinline__ uint32_t smem_to_u32(const void* p) {
    uint32_t a;
    asm("{ .reg .u64 t; cvta.to.shared.u64 t, %1; cvt.u32.u64 %0, t; }"
        : "=r"(a) : "l"(p));
    return a;
}

__device__ __forceinline__ void cp_async16(uint32_t s, const void* g) {
    asm volatile("cp.async.cg.shared.global [%0], [%1], 16;" :: "r"(s), "l"(g));
}
#define CP_COMMIT() asm volatile("cp.async.commit_group;" ::: "memory")

__device__ __forceinline__ void ldmx4(uint32_t& r0, uint32_t& r1,
                                      uint32_t& r2, uint32_t& r3, uint32_t a) {
    asm volatile("ldmatrix.sync.aligned.m8n8.x4.shared.b16 {%0,%1,%2,%3}, [%4];"
                 : "=r"(r0), "=r"(r1), "=r"(r2), "=r"(r3) : "r"(a));
}
__device__ __forceinline__ void ldmx4t(uint32_t& r0, uint32_t& r1,
                                       uint32_t& r2, uint32_t& r3, uint32_t a) {
    asm volatile("ldmatrix.sync.aligned.m8n8.x4.trans.shared.b16 {%0,%1,%2,%3}, [%4];"
                 : "=r"(r0), "=r"(r1), "=r"(r2), "=r"(r3) : "r"(a));
}

__device__ __forceinline__ void mma_f16(float& c0, float& c1, float& c2, float& c3,
                                        uint32_t a0, uint32_t a1, uint32_t a2, uint32_t a3,
                                        uint32_t b0, uint32_t b1) {
    asm volatile(
        "mma.sync.aligned.m16n8k16.row.col.f32.f16.f16.f32 "
        "{%0,%1,%2,%3}, {%4,%5,%6,%7}, {%8,%9}, {%0,%1,%2,%3};\n"
        : "+f"(c0), "+f"(c1), "+f"(c2), "+f"(c3)
        : "r"(a0), "r"(a1), "r"(a2), "r"(a3), "r"(b0), "r"(b1));
}

__device__ __forceinline__ float ex2f(float x) {
    float r;
    asm("ex2.approx.f32 %0, %1;" : "=f"(r) : "f"(x));
    return r;
}

__device__ __forceinline__ uint32_t pack_h2(float x, float y) {
    uint32_t r;
    asm("cvt.rn.f16x2.f32 %0, %1, %2;" : "=r"(r) : "f"(y), "f"(x));
    return r;
}

__device__ __forceinline__ void pack_hl(float x, float y, uint32_t& hh, uint32_t& ll) {
    __half hx = __float2half_rn(x), hy = __float2half_rn(y);
    __half lx = __float2half_rn(x - __half2float(hx));
    __half ly = __float2half_rn(y - __half2float(hy));
    __half2 H = __halves2half2(hx, hy), L = __halves2half2(lx, ly);
    hh = *(uint32_t*)&H; ll = *(uint32_t*)&L;
}

// ---------------------------------------------------------------------------
// fused split prepass: x and all weights -> fp16 hi only
// ---------------------------------------------------------------------------
__global__ void __launch_bounds__(256) split_all_kernel(
    const float* __restrict__ x,  const float* __restrict__ wq,
    const float* __restrict__ wk, const float* __restrict__ wv,
    const float* __restrict__ wp)
{
    const long long i4 = ((long long)blockIdx.x * 256 + threadIdx.x) * 4;
    const float* src; __half* dh; long long off;
    if (i4 < (long long)NX) {
        src = x; dh = g_xh; off = i4;
    } else {
        const long long r = i4 - (long long)NX;
        const int wsel = (int)(r >> 20);          // NW == 1<<20
        off = r & (long long)(NW - 1);
        switch (wsel) {
            case 0:  src = wq; dh = g_wqh; break;
            case 1:  src = wk; dh = g_wkh; break;
            case 2:  src = wv; dh = g_wvh; break;
            default: src = wp; dh = g_wph; break;
        }
    }
    float4 v = *(const float4*)(src + off);
    *(uint32_t*)(dh + off)     = pack_h2(v.x, v.y);
    *(uint32_t*)(dh + off + 2) = pack_h2(v.z, v.w);
}

// ---------------------------------------------------------------------------
// token-mask scan: per batch, inclusive counts + compact position list
// ---------------------------------------------------------------------------
__global__ void __launch_bounds__(256) mask_scan_kernel(const int* __restrict__ tmask)
{
    __shared__ int wsum[8];
    const int b = blockIdx.x;
    const int tid = threadIdx.x;
    const int lane = tid & 31, wid = tid >> 5;
    const int t0 = tid * 8;

    int v[8]; int s = 0;
    #pragma unroll
    for (int i = 0; i < 8; ++i) { v[i] = (tmask[b*T_ + t0 + i] != 0) ? 1 : 0; s += v[i]; }

    int sc = s;
    #pragma unroll
    for (int off = 1; off < 32; off <<= 1) {
        int n = __shfl_up_sync(0xffffffffu, sc, off);
        if (lane >= off) sc += n;
    }
    if (lane == 31) wsum[wid] = sc;
    __syncthreads();
    if (tid == 0) {
        int acc = 0;
        #pragma unroll
        for (int i = 0; i < 8; ++i) { acc += wsum[i]; wsum[i] = acc; }
    }
    __syncthreads();
    const int wbase = (wid > 0) ? wsum[wid - 1] : 0;
    int run = wbase + sc - s;
    #pragma unroll
    for (int i = 0; i < 8; ++i) {
        run += v[i];
        g_cnt[b*T_ + t0 + i] = run;
        if (v[i]) g_pos[b*T_ + run - 1] = t0 + i;
    }
}

// ---------------------------------------------------------------------------
// gather valid x rows (hi) into compacted buffer
// ---------------------------------------------------------------------------
__global__ void __launch_bounds__(128) gather_x_kernel()
{
    const int j = blockIdx.x, b = blockIdx.y;
    if (j >= g_cnt[b*T_ + T_ - 1]) return;
    const int src = g_pos[b*T_ + j];
    const size_t so = (size_t)(b*T_ + src) * C_;
    const size_t dofs = (size_t)(b*T_ + j) * C_;
    ((float4*)(g_xch + dofs))[threadIdx.x] = ((const float4*)(g_xh + so))[threadIdx.x];
}

// ---------------------------------------------------------------------------
// plain fp16 GEMM (fp32 acc): 128x128 tile, acc = Ah Wh^T + bias
// 3-stage cp.async ring, one __syncthreads per K-stage.
// ---------------------------------------------------------------------------
__device__ __forceinline__ void tc_gemm_tile(
    const __half* __restrict__ Ah, const __half* __restrict__ Wh,
    const float* __restrict__ bias,
    float* __restrict__ outF, __half* __restrict__ outH,
    __half* __restrict__ outL, float scale)
{
    const uint32_t sb = smem_to_u32(dyn_smem);

    const int tid  = threadIdx.x;
    const int wid  = tid >> 5;
    const int lane = tid & 31;
    const int g    = lane >> 2;
    const int tig  = lane & 3;

    const int row0 = blockIdx.y * 128;
    const int col0 = blockIdx.x * 128;
    const int warpM = (wid & 1) * 64;
    const int warpN = (wid >> 1) * 32;

    auto issue_chunk = [&](int st, uint32_t stage) {
        const int k0 = st * 32;
        #pragma unroll
        for (int p = 0; p < 2; ++p) {
            const int gid = tid + p * 256;
            const int r = gid >> 2, c = gid & 3;
            const uint32_t d = stage + (uint32_t)(r * PH + c * 8) * 2u;
            cp_async16(d,         Ah + (size_t)(row0 + r) * C_ + k0 + c * 8);
            cp_async16(d + TILEB, Wh + (size_t)(col0 + r) * C_ + k0 + c * 8);
        }
        CP_COMMIT();
    };

    float acc[4][4][4];
    #pragma unroll
    for (int mf = 0; mf < 4; ++mf)
        #pragma unroll
        for (int nf = 0; nf < 4; ++nf)
            #pragma unroll
            for (int r = 0; r < 4; ++r) acc[mf][nf][r] = 0.f;

    issue_chunk(0, sb);
    issue_chunk(1, sb + STAGEB);

    const int aRow = (lane & 15);
    const int aCol = (lane >> 4) << 3;
    const int bR4  = ((lane >> 4) << 3) + (lane & 7);
    const int bC4  = ((lane >> 3) & 1) << 3;

    int bufc = 0;
    int bufn = 2;
    for (int st = 0; st < 32; ++st) {
        if (st < 31) { asm volatile("cp.async.wait_group 1;" ::: "memory"); }
        else         { asm volatile("cp.async.wait_group 0;" ::: "memory"); }
        __syncthreads();

        if (st + 2 < 32) issue_chunk(st + 2, sb + (uint32_t)bufn * STAGEB);

        const uint32_t stage = sb + (uint32_t)bufc * STAGEB;
        bufc = (bufc == 2) ? 0 : bufc + 1;
        bufn = (bufn == 2) ? 0 : bufn + 1;

        #pragma unroll
        for (int kk = 0; kk < 2; ++kk) {
            const int k16 = kk * 16;

            uint32_t af[4][4];
            #pragma unroll
            for (int mf = 0; mf < 4; ++mf) {
                const uint32_t a = stage +
                    (uint32_t)((warpM + mf * 16 + aRow) * PH + k16 + aCol) * 2u;
                ldmx4(af[mf][0], af[mf][1], af[mf][2], af[mf][3], a);
            }
            uint32_t bh[2][4];
            #pragma unroll
            for (int np = 0; np < 2; ++np) {
                const uint32_t off =
                    (uint32_t)((warpN + np * 16 + bR4) * PH + k16 + bC4) * 2u;
                ldmx4(bh[np][0], bh[np][1], bh[np][2], bh[np][3],
                      stage + TILEB + off);
            }
            #pragma unroll
            for (int mf = 0; mf < 4; ++mf)
                #pragma unroll
                for (int np = 0; np < 2; ++np) {
                    mma_f16(acc[mf][2*np][0], acc[mf][2*np][1],
                            acc[mf][2*np][2], acc[mf][2*np][3],
                            af[mf][0], af[mf][1], af[mf][2], af[mf][3],
                            bh[np][0], bh[np][1]);
                    mma_f16(acc[mf][2*np+1][0], acc[mf][2*np+1][1],
                            acc[mf][2*np+1][2], acc[mf][2*np+1][3],
                            af[mf][0], af[mf][1], af[mf][2], af[mf][3],
                            bh[np][2], bh[np][3]);
                }
        }
    }

    #pragma unroll
    for (int nf = 0; nf < 4; ++nf) {
        const int colg = col0 + warpN + nf * 8 + tig * 2;
        const float2 bb = *(const float2*)&bias[colg];
        #pragma unroll
        for (int mf = 0; mf < 4; ++mf) {
            const int rowg = row0 + warpM + mf * 16 + g;
            const float v00 = acc[mf][nf][0] + bb.x, v01 = acc[mf][nf][1] + bb.y;
            const float v10 = acc[mf][nf][2] + bb.x, v11 = acc[mf][nf][3] + bb.y;
            if (outF) {
                *(float2*)&outF[(size_t)rowg * C_ + colg]       = make_float2(v00, v01);
                *(float2*)&outF[(size_t)(rowg + 8) * C_ + colg] = make_float2(v10, v11);
            } else if (outL) {
                uint32_t hh, ll;
                pack_hl(v00 * scale, v01 * scale, hh, ll);
                *(uint32_t*)&outH[(size_t)rowg * C_ + colg] = hh;
                *(uint32_t*)&outL[(size_t)rowg * C_ + colg] = ll;
                pack_hl(v10 * scale, v11 * scale, hh, ll);
                *(uint32_t*)&outH[(size_t)(rowg + 8) * C_ + colg] = hh;
                *(uint32_t*)&outL[(size_t)(rowg + 8) * C_ + colg] = ll;
            } else {
                *(uint32_t*)&outH[(size_t)rowg * C_ + colg] =
                    pack_h2(v00 * scale, v01 * scale);
                *(uint32_t*)&outH[(size_t)(rowg + 8) * C_ + colg] =
                    pack_h2(v10 * scale, v11 * scale);
            }
        }
    }
}

// Q scaled by (1/sqrt(D)) * log2(e) so softmax runs in exp2 domain
#define QSCALE (0.125f * 1.4426950408889634f)

// sel 0: Q (full rows, hi-only out); sel 1: K (split out); sel 2: V (hi-only)
__global__ void __launch_bounds__(256, 2) qkv_kernel(
    const float* __restrict__ bq, const float* __restrict__ bk,
    const float* __restrict__ bv)
{
    const int sel = blockIdx.z;
    if (sel != 0) {
        const int row0 = blockIdx.y * 128;
        const int b = row0 / T_;
        const int local = row0 - b * T_;
        if (local >= g_cnt[b*T_ + T_ - 1]) return;
    }
    const __half* Ah   = (sel == 0) ? g_xh  : g_xch;
    const __half* Wh   = (sel == 0) ? g_wqh : (sel == 1) ? g_wkh : g_wvh;
    const float*  bias = (sel == 0) ? bq    : (sel == 1) ? bk    : bv;
    __half* outH       = (sel == 0) ? g_qh  : (sel == 1) ? g_kch : g_vch;
    __half* outL       = (sel == 1) ? g_kcl : nullptr;
    const float scale  = (sel == 0) ? QSCALE : 1.0f;
    tc_gemm_tile(Ah, Wh, bias, nullptr, outH, outL, scale);
}

__global__ void __launch_bounds__(256, 2) proj_kernel(
    const float* __restrict__ bp, float* __restrict__ out)
{
    tc_gemm_tile(g_ah, g_wph, bp, out, nullptr, nullptr, 1.0f);
}

// ---------------------------------------------------------------------------
// flash attention over COMPACTED K/V: S = Qh(Kh+Kl), O += Ph Vh.
// ---------------------------------------------------------------------------
__global__ void __launch_bounds__(256, 2) attn_kernel()
{
    const uint32_t sb = smem_to_u32(dyn_smem);

    const int qt = (T_ / 128 - 1) - blockIdx.x;
    const int h = blockIdx.y, b = blockIdx.z;
    const int q0 = qt * 128;
    const int tid = threadIdx.x, w = tid >> 5, lane = tid & 31;
    const int g = lane >> 2, tig = lane & 3;
    const int rowBase = b * T_;
    const int hc = h * D_;

    // async-load Q tile (hi only)
    #pragma unroll
    for (int it = 0; it < 4; ++it) {
        const int gr = tid + it * 256;
        const int r = gr >> 3, c8 = (gr & 7) * 8;
        const size_t src = (size_t)(rowBase + q0 + r) * C_ + hc + c8;
        cp_async16(sb + QH_OFF + (uint32_t)(r * PQ + c8) * 2u, g_qh + src);
    }

    auto issueKV = [&](int kt, int buf) {
        const int k0 = kt * 64;
        const uint32_t base = sb + ST_OFF + (uint32_t)buf * STAGEA;
        #pragma unroll
        for (int it = 0; it < 2; ++it) {
            const int gr = tid + it * 256;
            const int r = gr >> 3, c8 = (gr & 7) * 8;
            const size_t src = (size_t)(rowBase + k0 + r) * C_ + hc + c8;
            const uint32_t d = base + (uint32_t)(r * PQ + c8) * 2u;
            cp_async16(d,              g_kch + src);
            cp_async16(d + KVTILE,     g_kcl + src);
            cp_async16(d + 2 * KVTILE, g_vch + src);
        }
        CP_COMMIT();
    };

    issueKV(0, 0);

    const int rA = q0 + w * 16 + g;
    const int rB = rA + 8;
    const int cntA = g_cnt[rowBase + rA];
    const int cntB = g_cnt[rowBase + rB];
    const int NVq  = g_cnt[rowBase + q0 + 127];
    const int nkt  = (NVq + 63) >> 6;

    float o[8][4];
    #pragma unroll
    for (int nf = 0; nf < 8; ++nf)
        #pragma unroll
        for (int c = 0; c < 4; ++c) o[nf][c] = 0.f;
    float mA = -1e30f, mB = -1e30f, lA = 0.f, lB = 0.f;

    const int aRow = lane & 15, aCol = (lane >> 4) << 3;
    const int bR4 = ((lane >> 4) << 3) + (lane & 7);   // K (non-trans)
    const int bC4 = ((lane >> 3) & 1) << 3;
    const int vR  = lane & 15;                          // V (trans)
    const int vC4 = (lane >> 4) << 3;

    for (int kt = 0; kt < nkt; ++kt) {
        const int buf = kt & 1;
        if (kt + 1 < nkt) {
            issueKV(kt + 1, buf ^ 1);
            asm volatile("cp.async.wait_group 1;" ::: "memory");
        } else {
            asm volatile("cp.async.wait_group 0;" ::: "memory");
        }
        __syncthreads();

        const int k0 = kt * 64;
        const uint32_t KH = sb + ST_OFF + (uint32_t)buf * STAGEA;
        const uint32_t KL = KH + KVTILE;
        const uint32_t VH = KH + 2 * KVTILE;

        // ---- S = Qh (Kh + Kl)^T ----
        float s[8][4];
        #pragma unroll
        for (int nf = 0; nf < 8; ++nf)
            #pragma unroll
            for (int c = 0; c < 4; ++c) s[nf][c] = 0.f;

        #pragma unroll
        for (int kk = 0; kk < 4; ++kk) {
            const int k16 = kk * 16;
            uint32_t aq[4];
            ldmx4(aq[0], aq[1], aq[2], aq[3],
                  sb + QH_OFF + (uint32_t)((w * 16 + aRow) * PQ + k16 + aCol) * 2u);
            #pragma unroll
            for (int np = 0; np < 4; ++np) {
                uint32_t bh[4], bl[4];
                const uint32_t off = (uint32_t)((np * 16 + bR4) * PQ + k16 + bC4) * 2u;
                ldmx4(bh[0], bh[1], bh[2], bh[3], KH + off);
                ldmx4(bl[0], bl[1], bl[2], bl[3], KL + off);
                mma_f16(s[2*np][0], s[2*np][1], s[2*np][2], s[2*np][3],
                        aq[0], aq[1], aq[2], aq[3], bh[0], bh[1]);
                mma_f16(s[2*np][0], s[2*np][1], s[2*np][2], s[2*np][3],
                        aq[0], aq[1], aq[2], aq[3], bl[0], bl[1]);
                mma_f16(s[2*np+1][0], s[2*np+1][1], s[2*np+1][2], s[2*np+1][3],
                        aq[0], aq[1], aq[2], aq[3], bh[2], bh[3]);
                mma_f16(s[2*np+1][0], s[2*np+1][1], s[2*np+1][2], s[2*np+1][3],
                        aq[0], aq[1], aq[2], aq[3], bl[2], bl[3]);
            }
        }

        // ---- unified mask: compact column index < cnt(row) ----
        #pragma unroll
        for (int nf = 0; nf < 8; ++nf) {
            const int c0 = k0 + nf * 8 + tig * 2;
            s[nf][0] = (c0     < cntA) ? s[nf][0] : -1e30f;
            s[nf][1] = (c0 + 1 < cntA) ? s[nf][1] : -1e30f;
            s[nf][2] = (c0     < cntB) ? s[nf][2] : -1e30f;
            s[nf][3] = (c0 + 1 < cntB) ? s[nf][3] : -1e30f;
        }

        // ---- online softmax (exp2 domain) ----
        float mxA = -1e30f, mxB = -1e30f;
        #pragma unroll
        for (int nf = 0; nf < 8; ++nf) {
            mxA = fmaxf(mxA, fmaxf(s[nf][0], s[nf][1]));
            mxB = fmaxf(mxB, fmaxf(s[nf][2], s[nf][3]));
        }
        mxA = fmaxf(mxA, __shfl_xor_sync(0xffffffffu, mxA, 1));
        mxA = fmaxf(mxA, __shfl_xor_sync(0xffffffffu, mxA, 2));
        mxB = fmaxf(mxB, __shfl_xor_sync(0xffffffffu, mxB, 1));
        mxB = fmaxf(mxB, __shfl_xor_sync(0xffffffffu, mxB, 2));
        const float mnA = fmaxf(mA, mxA), mnB = fmaxf(mB, mxB);
        const float cA = ex2f(mA - mnA), cB = ex2f(mB - mnB);
        mA = mnA; mB = mnB;
        float sA = 0.f, sB = 0.f;
        #pragma unroll
        for (int nf = 0; nf < 8; ++nf) {
            s[nf][0] = ex2f(s[nf][0] - mnA);
            s[nf][1] = ex2f(s[nf][1] - mnA);
            s[nf][2] = ex2f(s[nf][2] - mnB);
            s[nf][3] = ex2f(s[nf][3] - mnB);
            sA += s[nf][0] + s[nf][1];
            sB += s[nf][2] + s[nf][3];
        }
        sA += __shfl_xor_sync(0xffffffffu, sA, 1);
        sA += __shfl_xor_sync(0xffffffffu, sA, 2);
        sB += __shfl_xor_sync(0xffffffffu, sB, 1);
        sB += __shfl_xor_sync(0xffffffffu, sB, 2);
        lA = lA * cA + sA;
        lB = lB * cB + sB;
        #pragma unroll
        for (int nf = 0; nf < 8; ++nf) {
            o[nf][0] *= cA; o[nf][1] *= cA;
            o[nf][2] *= cB; o[nf][3] *= cB;
        }

        // ---- O += Ph Vh ----
        #pragma unroll
        for (int j = 0; j < 4; ++j) {
            uint32_t ph[4];
            ph[0] = pack_h2(s[2*j][0],   s[2*j][1]);
            ph[1] = pack_h2(s[2*j][2],   s[2*j][3]);
            ph[2] = pack_h2(s[2*j+1][0], s[2*j+1][1]);
            ph[3] = pack_h2(s[2*j+1][2], s[2*j+1][3]);
            #pragma unroll
            for (int np = 0; np < 4; ++np) {
                uint32_t bh[4];
                const uint32_t off = (uint32_t)((j * 16 + vR) * PQ + np * 16 + vC4) * 2u;
                ldmx4t(bh[0], bh[1], bh[2], bh[3], VH + off);
                mma_f16(o[2*np][0], o[2*np][1], o[2*np][2], o[2*np][3],
                        ph[0], ph[1], ph[2], ph[3], bh[0], bh[1]);
                mma_f16(o[2*np+1][0], o[2*np+1][1], o[2*np+1][2], o[2*np+1][3],
                        ph[0], ph[1], ph[2], ph[3], bh[2], bh[3]);
            }
        }
        __syncthreads();
    }

    // ---- normalize, fp16-hi output for proj GEMM ----
    const float invA = 1.f / lA, invB = 1.f / lB;
    #pragma unroll
    for (int nf = 0; nf < 8; ++nf) {
        const int col = hc + nf * 8 + tig * 2;
        const size_t iA = (size_t)(rowBase + rA) * C_ + col;
        const size_t iB = iA + (size_t)8 * C_;
        *(uint32_t*)&g_ah[iA] = pack_h2(o[nf][0] * invA, o[nf][1] * invA);
        *(uint32_t*)&g_ah[iB] = pack_h2(o[nf][2] * invB, o[nf][3] * invB);
    }
}

// ---------------------------------------------------------------------------
// Launch
// ---------------------------------------------------------------------------
extern "C" void kernel_launch(void* const* d_in, const int* in_sizes, int n_in,
                              void* d_out, int out_size)
{
    const float* x  = (const float*)d_in[0];
    const int*   tm = (const int*)  d_in[1];
    const float* wq = (const float*)d_in[2];
    const float* bq = (const float*)d_in[3];
    const float* wk = (const float*)d_in[4];
    const float* bk = (const float*)d_in[5];
    const float* wv = (const float*)d_in[6];
    const float* bv = (const float*)d_in[7];
    const float* wp = (const float*)d_in[8];
    const float* bp = (const float*)d_in[9];
    float* out = (float*)d_out;

    cudaFuncSetAttribute(qkv_kernel,  cudaFuncAttributeMaxDynamicSharedMemorySize, GSMEM);
    cudaFuncSetAttribute(proj_kernel, cudaFuncAttributeMaxDynamicSharedMemorySize, GSMEM);
    cudaFuncSetAttribute(attn_kernel, cudaFuncAttributeMaxDynamicSharedMemorySize, ATT_SMEM);

    const int nTot = (NX + 4 * NW) / 1024;
    split_all_kernel<<<nTot, 256>>>(x, wq, wk, wv, wp);
    mask_scan_kernel<<<B_, 256>>>(tm);

    dim3 gGx(T_, B_);
    gather_x_kernel<<<gGx, 128>>>();

    dim3 gQKV(C_/128, M_/128, 3);
    qkv_kernel<<<gQKV, 256, GSMEM>>>(bq, bk, bv);

    dim3 gAtt(T_/128, NH_, B_);
    attn_kernel<<<gAtt, 256, ATT_SMEM>>>();

    dim3 gProj(C_/128, M_/128, 1);
    proj_kernel<<<gProj, 256, GSMEM>>>(bp, out);
}

// round 17
// speedup vs baseline: 1.6993x; 1.1028x over previous
#include <cuda_runtime.h>
#include <cuda_fp16.h>
#include <cstdint>

#define B_  4
#define T_  2048
#define C_  1024
#define NH_ 16
#define D_  64
#define M_  (B_*T_)
#define NX  (M_*C_)
#define NW  (C_*C_)

// ---- GEMM smem (halves, pitch 40): 2 tiles/stage (Ah, Wh), 3 stages ----
#define PH     40
#define TILEB  10240u
#define STAGEB 20480u
#define GSMEM  61440

// ---- Attention smem: Qh 128x64 + 2 stages x (Kh,Vh) 64x64 ----
#define PQ 72
#define KVTILE 9216u               // 64*PQ*2
#define STAGEA 18432u              // 2 KV tiles
#define QH_OFF 0u
#define ST_OFF 18432u
#define ATT_SMEM 55296

extern __shared__ char dyn_smem[];

// Scratch (static device globals — no allocation at runtime)
__device__ __half g_qh[M_*C_];
__device__ __half g_ah[M_*C_];                  // attention out (hi only)
__device__ __half g_xh[M_*C_];                  // x hi
__device__ __half g_wqh[C_*C_];
__device__ __half g_wkh[C_*C_];
__device__ __half g_wvh[C_*C_];
__device__ __half g_wph[C_*C_];
// mask compaction
__device__ int    g_cnt[B_*T_];
__device__ int    g_pos[B_*T_];
// compacted K/V (hi only, written by K/V GEMM epilogue)
__device__ __half g_kch[M_*C_];
__device__ __half g_vch[M_*C_];

// ---------------------------------------------------------------------------
// helpers
// ---------------------------------------------------------------------------
__device__ __forceinline__ uint32_t smem_to_u32(const void* p) {
    uint32_t a;
    asm("{ .reg .u64 t; cvta.to.shared.u64 t, %1; cvt.u32.u64 %0, t; }"
        : "=r"(a) : "l"(p));
    return a;
}

__device__ __forceinline__ void cp_async16(uint32_t s, const void* g) {
    asm volatile("cp.async.cg.shared.global [%0], [%1], 16;" :: "r"(s), "l"(g));
}
#define CP_COMMIT() asm volatile("cp.async.commit_group;" ::: "memory")

__device__ __forceinline__ void ldmx4(uint32_t& r0, uint32_t& r1,
                                      uint32_t& r2, uint32_t& r3, uint32_t a) {
    asm volatile("ldmatrix.sync.aligned.m8n8.x4.shared.b16 {%0,%1,%2,%3}, [%4];"
                 : "=r"(r0), "=r"(r1), "=r"(r2), "=r"(r3) : "r"(a));
}
__device__ __forceinline__ void ldmx4t(uint32_t& r0, uint32_t& r1,
                                       uint32_t& r2, uint32_t& r3, uint32_t a) {
    asm volatile("ldmatrix.sync.aligned.m8n8.x4.trans.shared.b16 {%0,%1,%2,%3}, [%4];"
                 : "=r"(r0), "=r"(r1), "=r"(r2), "=r"(r3) : "r"(a));
}

__device__ __forceinline__ void mma_f16(float& c0, float& c1, float& c2, float& c3,
                                        uint32_t a0, uint32_t a1, uint32_t a2, uint32_t a3,
                                        uint32_t b0, uint32_t b1) {
    asm volatile(
        "mma.sync.aligned.m16n8k16.row.col.f32.f16.f16.f32 "
        "{%0,%1,%2,%3}, {%4,%5,%6,%7}, {%8,%9}, {%0,%1,%2,%3};\n"
        : "+f"(c0), "+f"(c1), "+f"(c2), "+f"(c3)
        : "r"(a0), "r"(a1), "r"(a2), "r"(a3), "r"(b0), "r"(b1));
}

__device__ __forceinline__ float ex2f(float x) {
    float r;
    asm("ex2.approx.f32 %0, %1;" : "=f"(r) : "f"(x));
    return r;
}

__device__ __forceinline__ uint32_t pack_h2(float x, float y) {
    uint32_t r;
    asm("cvt.rn.f16x2.f32 %0, %1, %2;" : "=r"(r) : "f"(y), "f"(x));
    return r;
}

// ---------------------------------------------------------------------------
// fused split prepass: x and all weights -> fp16 hi only
// ---------------------------------------------------------------------------
__global__ void __launch_bounds__(256) split_all_kernel(
    const float* __restrict__ x,  const float* __restrict__ wq,
    const float* __restrict__ wk, const float* __restrict__ wv,
    const float* __restrict__ wp)
{
    const long long i4 = ((long long)blockIdx.x * 256 + threadIdx.x) * 4;
    const float* src; __half* dh; long long off;
    if (i4 < (long long)NX) {
        src = x; dh = g_xh; off = i4;
    } else {
        const long long r = i4 - (long long)NX;
        const int wsel = (int)(r >> 20);          // NW == 1<<20
        off = r & (long long)(NW - 1);
        switch (wsel) {
            case 0:  src = wq; dh = g_wqh; break;
            case 1:  src = wk; dh = g_wkh; break;
            case 2:  src = wv; dh = g_wvh; break;
            default: src = wp; dh = g_wph; break;
        }
    }
    float4 v = *(const float4*)(src + off);
    *(uint32_t*)(dh + off)     = pack_h2(v.x, v.y);
    *(uint32_t*)(dh + off + 2) = pack_h2(v.z, v.w);
}

// ---------------------------------------------------------------------------
// token-mask scan: per batch, inclusive counts + compact position list
// ---------------------------------------------------------------------------
__global__ void __launch_bounds__(256) mask_scan_kernel(const int* __restrict__ tmask)
{
    __shared__ int wsum[8];
    const int b = blockIdx.x;
    const int tid = threadIdx.x;
    const int lane = tid & 31, wid = tid >> 5;
    const int t0 = tid * 8;

    int v[8]; int s = 0;
    #pragma unroll
    for (int i = 0; i < 8; ++i) { v[i] = (tmask[b*T_ + t0 + i] != 0) ? 1 : 0; s += v[i]; }

    int sc = s;
    #pragma unroll
    for (int off = 1; off < 32; off <<= 1) {
        int n = __shfl_up_sync(0xffffffffu, sc, off);
        if (lane >= off) sc += n;
    }
    if (lane == 31) wsum[wid] = sc;
    __syncthreads();
    if (tid == 0) {
        int acc = 0;
        #pragma unroll
        for (int i = 0; i < 8; ++i) { acc += wsum[i]; wsum[i] = acc; }
    }
    __syncthreads();
    const int wbase = (wid > 0) ? wsum[wid - 1] : 0;
    int run = wbase + sc - s;
    #pragma unroll
    for (int i = 0; i < 8; ++i) {
        run += v[i];
        g_cnt[b*T_ + t0 + i] = run;
        if (v[i]) g_pos[b*T_ + run - 1] = t0 + i;
    }
}

// ---------------------------------------------------------------------------
// plain fp16 GEMM (fp32 acc): 128x128 tile, acc = A Wh^T + bias.
// A rows optionally indirected through g_pos (compacted K/V GEMMs).
// 3-stage cp.async ring, one __syncthreads per K-stage.
// ---------------------------------------------------------------------------
__device__ __forceinline__ void tc_gemm_tile(
    const __half* __restrict__ Abase, bool indirect,
    const __half* __restrict__ Wh,
    const float* __restrict__ bias,
    float* __restrict__ outF, __half* __restrict__ outH, float scale)
{
    const uint32_t sb = smem_to_u32(dyn_smem);

    const int tid  = threadIdx.x;
    const int wid  = tid >> 5;
    const int lane = tid & 31;
    const int g    = lane >> 2;
    const int tig  = lane & 3;

    const int row0 = blockIdx.y * 128;
    const int col0 = blockIdx.x * 128;
    const int warpM = (wid & 1) * 64;
    const int warpN = (wid >> 1) * 32;

    // per-thread A source rows (k-invariant): rows tid>>2 and (tid>>2)+64
    const int r0t = tid >> 2, c8 = (tid & 3) * 8;
    const __half* aptr[2];
    #pragma unroll
    for (int p = 0; p < 2; ++p) {
        int r = row0 + r0t + p * 64;
        if (indirect) {
            const int b = r / T_;
            const int j = r - b * T_;
            const int cntT = g_cnt[b*T_ + T_ - 1];
            const int src = (j < cntT) ? g_pos[b*T_ + j] : 0;
            r = b * T_ + src;
        }
        aptr[p] = Abase + (size_t)r * C_ + c8;
    }
    const __half* wptr[2];
    #pragma unroll
    for (int p = 0; p < 2; ++p)
        wptr[p] = Wh + (size_t)(col0 + r0t + p * 64) * C_ + c8;

    auto issue_chunk = [&](int st, uint32_t stage) {
        const int k0 = st * 32;
        #pragma unroll
        for (int p = 0; p < 2; ++p) {
            const uint32_t d = stage + (uint32_t)((r0t + p * 64) * PH + c8) * 2u;
            cp_async16(d,         aptr[p] + k0);
            cp_async16(d + TILEB, wptr[p] + k0);
        }
        CP_COMMIT();
    };

    float acc[4][4][4];
    #pragma unroll
    for (int mf = 0; mf < 4; ++mf)
        #pragma unroll
        for (int nf = 0; nf < 4; ++nf)
            #pragma unroll
            for (int r = 0; r < 4; ++r) acc[mf][nf][r] = 0.f;

    issue_chunk(0, sb);
    issue_chunk(1, sb + STAGEB);

    const int aRow = (lane & 15);
    const int aCol = (lane >> 4) << 3;
    const int bR4  = ((lane >> 4) << 3) + (lane & 7);
    const int bC4  = ((lane >> 3) & 1) << 3;

    int bufc = 0;
    int bufn = 2;
    for (int st = 0; st < 32; ++st) {
        if (st < 31) { asm volatile("cp.async.wait_group 1;" ::: "memory"); }
        else         { asm volatile("cp.async.wait_group 0;" ::: "memory"); }
        __syncthreads();

        if (st + 2 < 32) issue_chunk(st + 2, sb + (uint32_t)bufn * STAGEB);

        const uint32_t stage = sb + (uint32_t)bufc * STAGEB;
        bufc = (bufc == 2) ? 0 : bufc + 1;
        bufn = (bufn == 2) ? 0 : bufn + 1;

        #pragma unroll
        for (int kk = 0; kk < 2; ++kk) {
            const int k16 = kk * 16;

            uint32_t af[4][4];
            #pragma unroll
            for (int mf = 0; mf < 4; ++mf) {
                const uint32_t a = stage +
                    (uint32_t)((warpM + mf * 16 + aRow) * PH + k16 + aCol) * 2u;
                ldmx4(af[mf][0], af[mf][1], af[mf][2], af[mf][3], a);
            }
            uint32_t bh[2][4];
            #pragma unroll
            for (int np = 0; np < 2; ++np) {
                const uint32_t off =
                    (uint32_t)((warpN + np * 16 + bR4) * PH + k16 + bC4) * 2u;
                ldmx4(bh[np][0], bh[np][1], bh[np][2], bh[np][3],
                      stage + TILEB + off);
            }
            #pragma unroll
            for (int mf = 0; mf < 4; ++mf)
                #pragma unroll
                for (int np = 0; np < 2; ++np) {
                    mma_f16(acc[mf][2*np][0], acc[mf][2*np][1],
                            acc[mf][2*np][2], acc[mf][2*np][3],
                            af[mf][0], af[mf][1], af[mf][2], af[mf][3],
                            bh[np][0], bh[np][1]);
                    mma_f16(acc[mf][2*np+1][0], acc[mf][2*np+1][1],
                            acc[mf][2*np+1][2], acc[mf][2*np+1][3],
                            af[mf][0], af[mf][1], af[mf][2], af[mf][3],
                            bh[np][2], bh[np][3]);
                }
        }
    }

    #pragma unroll
    for (int nf = 0; nf < 4; ++nf) {
        const int colg = col0 + warpN + nf * 8 + tig * 2;
        const float2 bb = *(const float2*)&bias[colg];
        #pragma unroll
        for (int mf = 0; mf < 4; ++mf) {
            const int rowg = row0 + warpM + mf * 16 + g;
            const float v00 = acc[mf][nf][0] + bb.x, v01 = acc[mf][nf][1] + bb.y;
            const float v10 = acc[mf][nf][2] + bb.x, v11 = acc[mf][nf][3] + bb.y;
            if (outF) {
                *(float2*)&outF[(size_t)rowg * C_ + colg]       = make_float2(v00, v01);
                *(float2*)&outF[(size_t)(rowg + 8) * C_ + colg] = make_float2(v10, v11);
            } else {
                *(uint32_t*)&outH[(size_t)rowg * C_ + colg] =
                    pack_h2(v00 * scale, v01 * scale);
                *(uint32_t*)&outH[(size_t)(rowg + 8) * C_ + colg] =
                    pack_h2(v10 * scale, v11 * scale);
            }
        }
    }
}

// Q scaled by (1/sqrt(D)) * log2(e) so softmax runs in exp2 domain
#define QSCALE (0.125f * 1.4426950408889634f)

// sel 0: Q (full rows); sel 1: K, sel 2: V (rows indirected via g_pos)
__global__ void __launch_bounds__(256, 2) qkv_kernel(
    const float* __restrict__ bq, const float* __restrict__ bk,
    const float* __restrict__ bv)
{
    const int sel = blockIdx.z;
    if (sel != 0) {
        const int row0 = blockIdx.y * 128;
        const int b = row0 / T_;
        const int local = row0 - b * T_;
        if (local >= g_cnt[b*T_ + T_ - 1]) return;
    }
    const __half* Wh   = (sel == 0) ? g_wqh : (sel == 1) ? g_wkh : g_wvh;
    const float*  bias = (sel == 0) ? bq    : (sel == 1) ? bk    : bv;
    __half* outH       = (sel == 0) ? g_qh  : (sel == 1) ? g_kch : g_vch;
    const float scale  = (sel == 0) ? QSCALE : 1.0f;
    tc_gemm_tile(g_xh, sel != 0, Wh, bias, nullptr, outH, scale);
}

__global__ void __launch_bounds__(256, 2) proj_kernel(
    const float* __restrict__ bp, float* __restrict__ out)
{
    tc_gemm_tile(g_ah, false, g_wph, bp, out, nullptr, 1.0f);
}

// ---------------------------------------------------------------------------
// plain fp16 flash attention over COMPACTED K/V: S = Qh Kh^T, O += Ph Vh.
// ---------------------------------------------------------------------------
__global__ void __launch_bounds__(256, 2) attn_kernel()
{
    const uint32_t sb = smem_to_u32(dyn_smem);

    const int qt = (T_ / 128 - 1) - blockIdx.x;
    const int h = blockIdx.y, b = blockIdx.z;
    const int q0 = qt * 128;
    const int tid = threadIdx.x, w = tid >> 5, lane = tid & 31;
    const int g = lane >> 2, tig = lane & 3;
    const int rowBase = b * T_;
    const int hc = h * D_;

    // async-load Q tile (hi only)
    #pragma unroll
    for (int it = 0; it < 4; ++it) {
        const int gr = tid + it * 256;
        const int r = gr >> 3, c8 = (gr & 7) * 8;
        const size_t src = (size_t)(rowBase + q0 + r) * C_ + hc + c8;
        cp_async16(sb + QH_OFF + (uint32_t)(r * PQ + c8) * 2u, g_qh + src);
    }

    auto issueKV = [&](int kt, int buf) {
        const int k0 = kt * 64;
        const uint32_t base = sb + ST_OFF + (uint32_t)buf * STAGEA;
        #pragma unroll
        for (int it = 0; it < 2; ++it) {
            const int gr = tid + it * 256;
            const int r = gr >> 3, c8 = (gr & 7) * 8;
            const size_t src = (size_t)(rowBase + k0 + r) * C_ + hc + c8;
            const uint32_t d = base + (uint32_t)(r * PQ + c8) * 2u;
            cp_async16(d,          g_kch + src);
            cp_async16(d + KVTILE, g_vch + src);
        }
        CP_COMMIT();
    };

    issueKV(0, 0);

    const int rA = q0 + w * 16 + g;
    const int rB = rA + 8;
    const int cntA = g_cnt[rowBase + rA];
    const int cntB = g_cnt[rowBase + rB];
    const int NVq  = g_cnt[rowBase + q0 + 127];
    const int nkt  = (NVq + 63) >> 6;

    float o[8][4];
    #pragma unroll
    for (int nf = 0; nf < 8; ++nf)
        #pragma unroll
        for (int c = 0; c < 4; ++c) o[nf][c] = 0.f;
    float mA = -1e30f, mB = -1e30f, lA = 0.f, lB = 0.f;

    const int aRow = lane & 15, aCol = (lane >> 4) << 3;
    const int bR4 = ((lane >> 4) << 3) + (lane & 7);   // K (non-trans)
    const int bC4 = ((lane >> 3) & 1) << 3;
    const int vR  = lane & 15;                          // V (trans)
    const int vC4 = (lane >> 4) << 3;

    for (int kt = 0; kt < nkt; ++kt) {
        const int buf = kt & 1;
        if (kt + 1 < nkt) {
            issueKV(kt + 1, buf ^ 1);
            asm volatile("cp.async.wait_group 1;" ::: "memory");
        } else {
            asm volatile("cp.async.wait_group 0;" ::: "memory");
        }
        __syncthreads();

        const int k0 = kt * 64;
        const uint32_t KH = sb + ST_OFF + (uint32_t)buf * STAGEA;
        const uint32_t VH = KH + KVTILE;

        // ---- S = Qh Kh^T ----
        float s[8][4];
        #pragma unroll
        for (int nf = 0; nf < 8; ++nf)
            #pragma unroll
            for (int c = 0; c < 4; ++c) s[nf][c] = 0.f;

        #pragma unroll
        for (int kk = 0; kk < 4; ++kk) {
            const int k16 = kk * 16;
            uint32_t aq[4];
            ldmx4(aq[0], aq[1], aq[2], aq[3],
                  sb + QH_OFF + (uint32_t)((w * 16 + aRow) * PQ + k16 + aCol) * 2u);
            #pragma unroll
            for (int np = 0; np < 4; ++np) {
                uint32_t bh[4];
                const uint32_t off = (uint32_t)((np * 16 + bR4) * PQ + k16 + bC4) * 2u;
                ldmx4(bh[0], bh[1], bh[2], bh[3], KH + off);
                mma_f16(s[2*np][0], s[2*np][1], s[2*np][2], s[2*np][3],
                        aq[0], aq[1], aq[2], aq[3], bh[0], bh[1]);
                mma_f16(s[2*np+1][0], s[2*np+1][1], s[2*np+1][2], s[2*np+1][3],
                        aq[0], aq[1], aq[2], aq[3], bh[2], bh[3]);
            }
        }

        // ---- unified mask: compact column index < cnt(row) ----
        #pragma unroll
        for (int nf = 0; nf < 8; ++nf) {
            const int c0 = k0 + nf * 8 + tig * 2;
            s[nf][0] = (c0     < cntA) ? s[nf][0] : -1e30f;
            s[nf][1] = (c0 + 1 < cntA) ? s[nf][1] : -1e30f;
            s[nf][2] = (c0     < cntB) ? s[nf][2] : -1e30f;
            s[nf][3] = (c0 + 1 < cntB) ? s[nf][3] : -1e30f;
        }

        // ---- online softmax (exp2 domain) ----
        float mxA = -1e30f, mxB = -1e30f;
        #pragma unroll
        for (int nf = 0; nf < 8; ++nf) {
            mxA = fmaxf(mxA, fmaxf(s[nf][0], s[nf][1]));
            mxB = fmaxf(mxB, fmaxf(s[nf][2], s[nf][3]));
        }
        mxA = fmaxf(mxA, __shfl_xor_sync(0xffffffffu, mxA, 1));
        mxA = fmaxf(mxA, __shfl_xor_sync(0xffffffffu, mxA, 2));
        mxB = fmaxf(mxB, __shfl_xor_sync(0xffffffffu, mxB, 1));
        mxB = fmaxf(mxB, __shfl_xor_sync(0xffffffffu, mxB, 2));
        const float mnA = fmaxf(mA, mxA), mnB = fmaxf(mB, mxB);
        const float cA = ex2f(mA - mnA), cB = ex2f(mB - mnB);
        mA = mnA; mB = mnB;
        float sA = 0.f, sB = 0.f;
        #pragma unroll
        for (int nf = 0; nf < 8; ++nf) {
            s[nf][0] = ex2f(s[nf][0] - mnA);
            s[nf][1] = ex2f(s[nf][1] - mnA);
            s[nf][2] = ex2f(s[nf][2] - mnB);
            s[nf][3] = ex2f(s[nf][3] - mnB);
            sA += s[nf][0] + s[nf][1];
            sB += s[nf][2] + s[nf][3];
        }
        sA += __shfl_xor_sync(0xffffffffu, sA, 1);
        sA += __shfl_xor_sync(0xffffffffu, sA, 2);
        sB += __shfl_xor_sync(0xffffffffu, sB, 1);
        sB += __shfl_xor_sync(0xffffffffu, sB, 2);
        lA = lA * cA + sA;
        lB = lB * cB + sB;
        #pragma unroll
        for (int nf = 0; nf < 8; ++nf) {
            o[nf][0] *= cA; o[nf][1] *= cA;
            o[nf][2] *= cB; o[nf][3] *= cB;
        }

        // ---- O += Ph Vh ----
        #pragma unroll
        for (int j = 0; j < 4; ++j) {
            uint32_t ph[4];
            ph[0] = pack_h2(s[2*j][0],   s[2*j][1]);
            ph[1] = pack_h2(s[2*j][2],   s[2*j][3]);
            ph[2] = pack_h2(s[2*j+1][0], s[2*j+1][1]);
            ph[3] = pack_h2(s[2*j+1][2], s[2*j+1][3]);
            #pragma unroll
            for (int np = 0; np < 4; ++np) {
                uint32_t bh[4];
                const uint32_t off = (uint32_t)((j * 16 + vR) * PQ + np * 16 + vC4) * 2u;
                ldmx4t(bh[0], bh[1], bh[2], bh[3], VH + off);
                mma_f16(o[2*np][0], o[2*np][1], o[2*np][2], o[2*np][3],
                        ph[0], ph[1], ph[2], ph[3], bh[0], bh[1]);
                mma_f16(o[2*np+1][0], o[2*np+1][1], o[2*np+1][2], o[2*np+1][3],
                        ph[0], ph[1], ph[2], ph[3], bh[2], bh[3]);
            }
        }
        __syncthreads();
    }

    // ---- normalize, fp16-hi output for proj GEMM ----
    const float invA = 1.f / lA, invB = 1.f / lB;
    #pragma unroll
    for (int nf = 0; nf < 8; ++nf) {
        const int col = hc + nf * 8 + tig * 2;
        const size_t iA = (size_t)(rowBase + rA) * C_ + col;
        const size_t iB = iA + (size_t)8 * C_;
        *(uint32_t*)&g_ah[iA] = pack_h2(o[nf][0] * invA, o[nf][1] * invA);
        *(uint32_t*)&g_ah[iB] = pack_h2(o[nf][2] * invB, o[nf][3] * invB);
    }
}

// ---------------------------------------------------------------------------
// Launch
// ---------------------------------------------------------------------------
extern "C" void kernel_launch(void* const* d_in, const int* in_sizes, int n_in,
                              void* d_out, int out_size)
{
    const float* x  = (const float*)d_in[0];
    const int*   tm = (const int*)  d_in[1];
    const float* wq = (const float*)d_in[2];
    const float* bq = (const float*)d_in[3];
    const float* wk = (const float*)d_in[4];
    const float* bk = (const float*)d_in[5];
    const float* wv = (const float*)d_in[6];
    const float* bv = (const float*)d_in[7];
    const float* wp = (const float*)d_in[8];
    const float* bp = (const float*)d_in[9];
    float* out = (float*)d_out;

    cudaFuncSetAttribute(qkv_kernel,  cudaFuncAttributeMaxDynamicSharedMemorySize, GSMEM);
    cudaFuncSetAttribute(proj_kernel, cudaFuncAttributeMaxDynamicSharedMemorySize, GSMEM);
    cudaFuncSetAttribute(attn_kernel, cudaFuncAttributeMaxDynamicSharedMemorySize, ATT_SMEM);

    const int nTot = (NX + 4 * NW) / 1024;
    split_all_kernel<<<nTot, 256>>>(x, wq, wk, wv, wp);
    mask_scan_kernel<<<B_, 256>>>(tm);

    dim3 gQKV(C_/128, M_/128, 3);
    qkv_kernel<<<gQKV, 256, GSMEM>>>(bq, bk, bv);

    dim3 gAtt(T_/128, NH_, B_);
    attn_kernel<<<gAtt, 256, ATT_SMEM>>>();

    dim3 gProj(C_/128, M_/128, 1);
    proj_kernel<<<gProj, 256, GSMEM>>>(bp, out);
}